// round 2
// baseline (speedup 1.0000x reference)
#include <cuda_runtime.h>
#include <math.h>

#define NMAX   20000
#define ETOT_MAX 340000
#define DD     256
#define NGRAPH 16

// ---------------- scratch (static device globals; no allocation) -------------
__device__ float g_X[NMAX * DD];        // current features (layer input/output)
__device__ float g_H[NMAX * DD];        // post-GEMM transformed features
__device__ float g_ebuf[ETOT_MAX * 4];  // per-edge e/exp/alpha scratch (4 heads L1)
__device__ float g_as[NMAX * 4];        // per-node source attention logits
__device__ float g_ad[NMAX * 4];        // per-node dest   attention logits
__device__ int   g_deg[NMAX];
__device__ int   g_row[NMAX + 1];
__device__ int   g_cur[NMAX];
__device__ int   g_col[ETOT_MAX];       // src node per CSR slot
__device__ int   g_eid[ETOT_MAX];       // original edge id per CSR slot
__device__ float g_cs[4], g_cd[4];      // layer-1 collapsed attention weights
__device__ float g_gsum[NGRAPH * DD];
__device__ int   g_gcnt[NGRAPH];
__device__ int   g_is64;                // 1 if edge_index/batch are int64

// ---------------- helpers ----------------------------------------------------
__device__ __forceinline__ float geluf(float x) {
    float t = tanhf(0.7978845608028654f * (x + 0.044715f * x * x * x));
    return 0.5f * x * (1.0f + t);
}
__device__ __forceinline__ float lrelu(float x) { return x > 0.f ? x : 0.2f * x; }

// dtype-agnostic index load (int32 vs int64, flag in g_is64)
__device__ __forceinline__ long long load_idx(const void* p, long long i) {
    if (g_is64) return ((const long long*)p)[i];
    return (long long)((const int*)p)[i];
}

// ---------------- dtype detection --------------------------------------------
// If data is int64 with small non-negative values, every odd 32-bit word is 0.
// If int32, odd words are real indices (nonzero with overwhelming probability).
__global__ void k_detect(const int* __restrict__ w32, int nwords) {
    __shared__ int nz;
    if (threadIdx.x == 0) nz = 0;
    __syncthreads();
    int pairs = nwords >> 1;
    int lim = min(pairs, 4096);
    for (int i = threadIdx.x; i < lim; i += blockDim.x)
        if (w32[2 * i + 1] != 0) nz = 1;
    __syncthreads();
    if (threadIdx.x == 0) g_is64 = (nz == 0) ? 1 : 0;
}

// ---------------- CSR construction -------------------------------------------
__global__ void k_zero_deg(int n) {
    int i = blockIdx.x * blockDim.x + threadIdx.x;
    if (i < n) g_deg[i] = 0;
}
__global__ void k_count(const void* __restrict__ ei, int E, int Etot, int n) {
    int e = blockIdx.x * blockDim.x + threadIdx.x;
    if (e >= Etot) return;
    int dst = (e < E) ? (int)load_idx(ei, (long long)E + e) : (e - E);
    if (dst >= 0 && dst < n) atomicAdd(&g_deg[dst], 1);
}
__global__ void k_scan(int n) {
    __shared__ int s[1024];
    int t = threadIdx.x;
    int chunk = (n + 1023) >> 10;
    int b0 = t * chunk, b1 = min(b0 + chunk, n);
    int sum = 0;
    for (int i = b0; i < b1; i++) sum += g_deg[i];
    s[t] = sum; __syncthreads();
    int val = sum;
    for (int off = 1; off < 1024; off <<= 1) {
        int v = (t >= off) ? s[t - off] : 0;
        __syncthreads();
        s[t] += v; __syncthreads();
    }
    int run = s[t] - val;            // exclusive prefix
    for (int i = b0; i < b1; i++) {
        g_row[i] = run; g_cur[i] = run; run += g_deg[i];
    }
    if (t == 0) g_row[n] = s[1023];
}
__global__ void k_fill(const void* __restrict__ ei, int E, int Etot, int n) {
    int e = blockIdx.x * blockDim.x + threadIdx.x;
    if (e >= Etot) return;
    int src, dst;
    if (e < E) {
        src = (int)load_idx(ei, e);
        dst = (int)load_idx(ei, (long long)E + e);
    } else { src = e - E; dst = e - E; }
    if (dst < 0 || dst >= n || src < 0 || src >= n) return;
    int pos = atomicAdd(&g_cur[dst], 1);
    g_col[pos] = src;
    g_eid[pos] = e;
}

// ---------------- layer 1 (rank-1, 4 heads) ----------------------------------
__global__ void k_prep1(const float* __restrict__ W1, const float* __restrict__ as1,
                        const float* __restrict__ ad1) {
    __shared__ float ss[256], sd[256];
    int c = threadIdx.x;
    float w = W1[c];
    ss[c] = w * as1[c];
    sd[c] = w * ad1[c];
    __syncthreads();
    for (int off = 32; off; off >>= 1) {
        if ((c & 63) < off) { ss[c] += ss[c + off]; sd[c] += sd[c + off]; }
        __syncthreads();
    }
    if ((c & 63) == 0) { g_cs[c >> 6] = ss[c]; g_cd[c >> 6] = sd[c]; }
}
__global__ void k_sd1(const float* __restrict__ x, int n) {
    int i = blockIdx.x * blockDim.x + threadIdx.x;
    if (i >= n) return;
    float xv = x[i];
    #pragma unroll
    for (int h = 0; h < 4; h++) {
        g_as[i * 4 + h] = xv * g_cs[h];
        g_ad[i * 4 + h] = xv * g_cd[h];
    }
}
__global__ void k_att1(int n) {
    int w = (blockIdx.x * blockDim.x + threadIdx.x) >> 5;
    int lane = threadIdx.x & 31;
    if (w >= n) return;
    int b = g_row[w], e2 = g_row[w + 1];
    float4 ad = ((const float4*)g_ad)[w];
    float4 mx = make_float4(-1e30f, -1e30f, -1e30f, -1e30f);
    for (int p = b + lane; p < e2; p += 32) {
        float4 av = ((const float4*)g_as)[g_col[p]];
        float4 ev;
        ev.x = lrelu(av.x + ad.x); ev.y = lrelu(av.y + ad.y);
        ev.z = lrelu(av.z + ad.z); ev.w = lrelu(av.w + ad.w);
        ((float4*)g_ebuf)[p] = ev;
        mx.x = fmaxf(mx.x, ev.x); mx.y = fmaxf(mx.y, ev.y);
        mx.z = fmaxf(mx.z, ev.z); mx.w = fmaxf(mx.w, ev.w);
    }
    for (int o = 16; o; o >>= 1) {
        mx.x = fmaxf(mx.x, __shfl_xor_sync(0xffffffffu, mx.x, o));
        mx.y = fmaxf(mx.y, __shfl_xor_sync(0xffffffffu, mx.y, o));
        mx.z = fmaxf(mx.z, __shfl_xor_sync(0xffffffffu, mx.z, o));
        mx.w = fmaxf(mx.w, __shfl_xor_sync(0xffffffffu, mx.w, o));
    }
    float4 sm = make_float4(0, 0, 0, 0);
    for (int p = b + lane; p < e2; p += 32) {
        float4 ev = ((float4*)g_ebuf)[p];
        ev.x = expf(ev.x - mx.x); ev.y = expf(ev.y - mx.y);
        ev.z = expf(ev.z - mx.z); ev.w = expf(ev.w - mx.w);
        ((float4*)g_ebuf)[p] = ev;
        sm.x += ev.x; sm.y += ev.y; sm.z += ev.z; sm.w += ev.w;
    }
    for (int o = 16; o; o >>= 1) {
        sm.x += __shfl_xor_sync(0xffffffffu, sm.x, o);
        sm.y += __shfl_xor_sync(0xffffffffu, sm.y, o);
        sm.z += __shfl_xor_sync(0xffffffffu, sm.z, o);
        sm.w += __shfl_xor_sync(0xffffffffu, sm.w, o);
    }
    float4 inv;
    inv.x = 1.f / (sm.x + 1e-16f); inv.y = 1.f / (sm.y + 1e-16f);
    inv.z = 1.f / (sm.z + 1e-16f); inv.w = 1.f / (sm.w + 1e-16f);
    for (int p = b + lane; p < e2; p += 32) {
        float4 ev = ((float4*)g_ebuf)[p];
        ev.x *= inv.x; ev.y *= inv.y; ev.z *= inv.z; ev.w *= inv.w;
        ((float4*)g_ebuf)[p] = ev;
    }
}
__global__ void __launch_bounds__(256) k_agg1(const float* __restrict__ x,
                                              const float* __restrict__ W1,
                                              const float* __restrict__ b1, int n) {
    int d = blockIdx.x;
    if (d >= n) return;
    int tid = threadIdx.x;
    __shared__ float s4[4];
    if (tid < 32) {
        int b = g_row[d], e = g_row[d + 1];
        float4 acc = make_float4(0, 0, 0, 0);
        for (int p = b + tid; p < e; p += 32) {
            float4 al = ((const float4*)g_ebuf)[p];
            float xv = x[g_col[p]];
            acc.x += al.x * xv; acc.y += al.y * xv;
            acc.z += al.z * xv; acc.w += al.w * xv;
        }
        for (int o = 16; o; o >>= 1) {
            acc.x += __shfl_xor_sync(0xffffffffu, acc.x, o);
            acc.y += __shfl_xor_sync(0xffffffffu, acc.y, o);
            acc.z += __shfl_xor_sync(0xffffffffu, acc.z, o);
            acc.w += __shfl_xor_sync(0xffffffffu, acc.w, o);
        }
        if (tid == 0) { s4[0] = acc.x; s4[1] = acc.y; s4[2] = acc.z; s4[3] = acc.w; }
    }
    __syncthreads();
    g_X[d * 256 + tid] = geluf(s4[tid >> 6] * W1[tid] + b1[tid]);
}

// ---------------- dense GEMM: g_H = g_X @ W  (M x 256 x 256) -----------------
__global__ void __launch_bounds__(256) k_gemm(const float* __restrict__ B, int M) {
    __shared__ float As[16][128];
    __shared__ float Bs[16][64];
    int m0 = blockIdx.x * 128;
    int n0 = blockIdx.y * 64;
    int tid = threadIdx.x;
    int ty = tid >> 4, tx = tid & 15;
    float acc[8][4];
    #pragma unroll
    for (int r = 0; r < 8; r++)
        #pragma unroll
        for (int c = 0; c < 4; c++) acc[r][c] = 0.f;

    for (int k0 = 0; k0 < 256; k0 += 16) {
        #pragma unroll
        for (int i = 0; i < 2; i++) {
            int idx = tid + i * 256;
            int ar = idx >> 2, kq = idx & 3;
            float4 v = make_float4(0, 0, 0, 0);
            int gr = m0 + ar;
            if (gr < M) v = *(const float4*)(&g_X[gr * 256 + k0 + kq * 4]);
            As[kq * 4 + 0][ar] = v.x; As[kq * 4 + 1][ar] = v.y;
            As[kq * 4 + 2][ar] = v.z; As[kq * 4 + 3][ar] = v.w;
        }
        {
            float4 v = *(const float4*)(&B[(k0 + (tid >> 4)) * 256 + n0 + (tid & 15) * 4]);
            *(float4*)(&Bs[tid >> 4][(tid & 15) * 4]) = v;
        }
        __syncthreads();
        #pragma unroll
        for (int k = 0; k < 16; k++) {
            float a[8], bb[4];
            #pragma unroll
            for (int r = 0; r < 8; r++) a[r] = As[k][ty * 8 + r];
            #pragma unroll
            for (int c = 0; c < 4; c++) bb[c] = Bs[k][tx * 4 + c];
            #pragma unroll
            for (int r = 0; r < 8; r++)
                #pragma unroll
                for (int c = 0; c < 4; c++) acc[r][c] += a[r] * bb[c];
        }
        __syncthreads();
    }
    #pragma unroll
    for (int r = 0; r < 8; r++) {
        int gr = m0 + ty * 8 + r;
        if (gr < M) {
            float4 v = make_float4(acc[r][0], acc[r][1], acc[r][2], acc[r][3]);
            *(float4*)(&g_H[gr * 256 + n0 + tx * 4]) = v;
        }
    }
}

// ---------------- per-node attention logits (layers 2-4) ---------------------
__global__ void k_sd(const float* __restrict__ av, const float* __restrict__ dv, int n) {
    int w = (blockIdx.x * blockDim.x + threadIdx.x) >> 5;
    int lane = threadIdx.x & 31;
    if (w >= n) return;
    const float4* h = (const float4*)(&g_H[w * 256]);
    float sa = 0.f, sd_ = 0.f;
    #pragma unroll
    for (int i = 0; i < 2; i++) {
        float4 hv = h[lane * 2 + i];
        float4 a = ((const float4*)av)[lane * 2 + i];
        float4 d = ((const float4*)dv)[lane * 2 + i];
        sa  += hv.x * a.x + hv.y * a.y + hv.z * a.z + hv.w * a.w;
        sd_ += hv.x * d.x + hv.y * d.y + hv.z * d.z + hv.w * d.w;
    }
    for (int o = 16; o; o >>= 1) {
        sa  += __shfl_xor_sync(0xffffffffu, sa, o);
        sd_ += __shfl_xor_sync(0xffffffffu, sd_, o);
    }
    if (lane == 0) { g_as[w] = sa; g_ad[w] = sd_; }
}

// ---------------- edge softmax (heads=1), warp per dst -----------------------
__global__ void k_att2(int n, float* alpha_out) {
    int d = (blockIdx.x * blockDim.x + threadIdx.x) >> 5;
    int lane = threadIdx.x & 31;
    if (d >= n) return;
    int b = g_row[d], e = g_row[d + 1];
    float ad = g_ad[d];
    float mx = -1e30f;
    for (int p = b + lane; p < e; p += 32) {
        float ev = lrelu(g_as[g_col[p]] + ad);
        g_ebuf[p] = ev;
        mx = fmaxf(mx, ev);
    }
    for (int o = 16; o; o >>= 1) mx = fmaxf(mx, __shfl_xor_sync(0xffffffffu, mx, o));
    float sm = 0.f;
    for (int p = b + lane; p < e; p += 32) {
        float ex = expf(g_ebuf[p] - mx);
        g_ebuf[p] = ex;
        sm += ex;
    }
    for (int o = 16; o; o >>= 1) sm += __shfl_xor_sync(0xffffffffu, sm, o);
    float inv = 1.f / (sm + 1e-16f);
    for (int p = b + lane; p < e; p += 32) {
        float al = g_ebuf[p] * inv;
        g_ebuf[p] = al;
        if (alpha_out) alpha_out[g_eid[p]] = al;
    }
}

// ---------------- aggregation (heads=1): block per dst, thread per channel ---
__global__ void __launch_bounds__(256) k_agg2(const float* __restrict__ bias, int n) {
    int d = blockIdx.x;
    if (d >= n) return;
    int c = threadIdx.x;
    int b = g_row[d], e = g_row[d + 1];
    __shared__ float sal[64];
    __shared__ int scol[64];
    float acc = 0.f;
    for (int base = b; base < e; base += 64) {
        int lim = min(64, e - base);
        if (c < lim) { sal[c] = g_ebuf[base + c]; scol[c] = g_col[base + c]; }
        __syncthreads();
        for (int i = 0; i < lim; i++) acc += sal[i] * g_H[scol[i] * 256 + c];
        __syncthreads();
    }
    g_X[d * 256 + c] = geluf(acc + bias[c]);
}

// ---------------- pooling + MLP -----------------------------------------------
__global__ void k_zero_pool() {
    int i = blockIdx.x * blockDim.x + threadIdx.x;
    if (i < NGRAPH * DD) g_gsum[i] = 0.f;
    if (i < NGRAPH) g_gcnt[i] = 0;
}
__global__ void k_gcnt(const void* __restrict__ batch, int n) {
    int i = blockIdx.x * blockDim.x + threadIdx.x;
    if (i < n) {
        int g = (int)load_idx(batch, i);
        if (g >= 0 && g < NGRAPH) atomicAdd(&g_gcnt[g], 1);
    }
}
__global__ void __launch_bounds__(256) k_pool(const void* __restrict__ batch, int n) {
    int n0 = blockIdx.x * 64;
    int c = threadIdx.x;
    if (n0 >= n) return;
    int g = (int)load_idx(batch, n0);
    float acc = 0.f;
    int lim = min(64, n - n0);
    for (int i = 0; i < lim; i++) {
        int node = n0 + i;
        int bg = (int)load_idx(batch, node);
        if (bg != g) { atomicAdd(&g_gsum[g * 256 + c], acc); acc = 0.f; g = bg; }
        acc += g_X[node * 256 + c];
    }
    atomicAdd(&g_gsum[g * 256 + c], acc);
}
__global__ void __launch_bounds__(512) k_mlp(const float* __restrict__ Wl1, const float* __restrict__ bl1,
                                             const float* __restrict__ Wl2, const float* __restrict__ bl2,
                                             const float* __restrict__ Wl3, const float* __restrict__ bl3,
                                             float* __restrict__ out) {
    __shared__ float G[16 * 256];
    __shared__ float G1[16 * 128];
    __shared__ float G2[16 * 64];
    int t = threadIdx.x;
    for (int i = t; i < 4096; i += 512) {
        int cnt = g_gcnt[i >> 8];
        G[i] = g_gsum[i] / (float)(cnt > 0 ? cnt : 1);
    }
    __syncthreads();
    for (int i = t; i < 2048; i += 512) {
        int gi = i >> 7, j = i & 127;
        float a = bl1[j];
        for (int k = 0; k < 256; k++) a += G[gi * 256 + k] * Wl1[k * 128 + j];
        G1[i] = geluf(a);
    }
    __syncthreads();
    for (int i = t; i < 1024; i += 512) {
        int gi = i >> 6, j = i & 63;
        float a = bl2[j];
        for (int k = 0; k < 128; k++) a += G1[gi * 128 + k] * Wl2[k * 64 + j];
        G2[i] = geluf(a);
    }
    __syncthreads();
    if (t < 16) {
        float a = bl3[0];
        for (int k = 0; k < 64; k++) a += G2[t * 64 + k] * Wl3[k];
        out[t] = 1.f / (1.f + expf(-a));
    }
}

// ---------------- attn_edge_index output --------------------------------------
__global__ void k_attn_idx(const void* __restrict__ ei, int E, int Etot,
                           float* __restrict__ dst) {
    int i = blockIdx.x * blockDim.x + threadIdx.x;
    if (i >= 2 * Etot) return;
    int which = i / Etot;        // 0 = src row, 1 = dst row
    int e = i - which * Etot;
    long long v = (e < E) ? load_idx(ei, (long long)which * E + e)
                          : (long long)(e - E);
    dst[i] = (float)v;
}

// ---------------- host launcher ------------------------------------------------
extern "C" void kernel_launch(void* const* d_in, const int* in_sizes, int n_in,
                              void* d_out, int out_size) {
    const float* x     = (const float*)d_in[0];
    const void*  ei    = d_in[1];
    const void*  batch = d_in[2];
    const float* W1  = (const float*)d_in[3];
    const float* as1 = (const float*)d_in[4];
    const float* ad1 = (const float*)d_in[5];
    const float* b1  = (const float*)d_in[6];
    const float* W2  = (const float*)d_in[7];
    const float* as2 = (const float*)d_in[8];
    const float* ad2 = (const float*)d_in[9];
    const float* b2  = (const float*)d_in[10];
    const float* Wl1 = (const float*)d_in[11];
    const float* bl1 = (const float*)d_in[12];
    const float* Wl2 = (const float*)d_in[13];
    const float* bl2 = (const float*)d_in[14];
    const float* Wl3 = (const float*)d_in[15];
    const float* bl3 = (const float*)d_in[16];

    int Nn = in_sizes[0];          // nodes (x is [N,1])
    int E = in_sizes[1] / 2;       // edges
    int Etot = E + Nn;             // with self-loops
    float* out = (float*)d_out;
    bool full = (out_size >= 16 + 3 * Etot);
    float* alpha_out = full ? (out + 16 + 2 * Etot) : nullptr;

    // ---- dtype detection (int32 vs int64 edge/batch arrays) ----
    k_detect<<<1, 256>>>((const int*)ei, 2 * E);

    // ---- CSR (counting sort by dst) ----
    k_zero_deg<<<(Nn + 255) / 256, 256>>>(Nn);
    k_count<<<(Etot + 255) / 256, 256>>>(ei, E, Etot, Nn);
    k_scan<<<1, 1024>>>(Nn);
    k_fill<<<(Etot + 255) / 256, 256>>>(ei, E, Etot, Nn);

    // ---- layer 1 (GATConv(1, 64, heads=4), rank-1 collapse) ----
    k_prep1<<<1, 256>>>(W1, as1, ad1);
    k_sd1<<<(Nn + 255) / 256, 256>>>(x, Nn);
    k_att1<<<(Nn + 7) / 8, 256>>>(Nn);
    k_agg1<<<Nn, 256>>>(x, W1, b1, Nn);

    // ---- layers 2-4 (GATConv(256, 256, heads=1)) ----
    for (int l = 0; l < 3; l++) {
        k_gemm<<<dim3((Nn + 127) / 128, 4), 256>>>(W2 + l * 65536, Nn);
        k_sd<<<(Nn + 7) / 8, 256>>>(as2 + l * 256, ad2 + l * 256, Nn);
        k_att2<<<(Nn + 7) / 8, 256>>>(Nn, (l == 2) ? alpha_out : nullptr);
        k_agg2<<<Nn, 256>>>(b2 + l * 256, Nn);
    }

    // ---- mean pool + MLP head ----
    k_zero_pool<<<17, 256>>>();
    k_gcnt<<<(Nn + 255) / 256, 256>>>(batch, Nn);
    k_pool<<<(Nn + 63) / 64, 256>>>(batch, Nn);
    k_mlp<<<1, 512>>>(Wl1, bl1, Wl2, bl2, Wl3, bl3, out);

    // ---- attn_edge_index output ----
    if (full) k_attn_idx<<<(2 * Etot + 255) / 256, 256>>>(ei, E, Etot, out + 16);
}

// round 3
// speedup vs baseline: 1.3112x; 1.3112x over previous
#include <cuda_runtime.h>
#include <math.h>

#define NMAX   20000
#define ETOT_MAX 340000
#define DD     256
#define NGRAPH 16

// ---------------- scratch (static device globals; no allocation) -------------
__device__ float g_X[NMAX * DD];        // current features (layer input/output)
__device__ float g_H[NMAX * DD];        // post-GEMM transformed features
__device__ float g_ebuf[ETOT_MAX * 4];  // per-edge e/exp/alpha scratch (4 heads L1)
__device__ float g_as[NMAX * 4];        // per-node source attention logits
__device__ float g_ad[NMAX * 4];        // per-node dest   attention logits
__device__ int   g_deg[NMAX];
__device__ int   g_row[NMAX + 1];
__device__ int   g_cur[NMAX];
__device__ int   g_col[ETOT_MAX];       // src node per CSR slot
__device__ int   g_eid[ETOT_MAX];       // original edge id per CSR slot
__device__ float g_cs[4], g_cd[4];      // layer-1 collapsed attention weights
__device__ float g_gsum[NGRAPH * DD];
__device__ int   g_gcnt[NGRAPH];
__device__ int   g_is64;                // 1 if edge_index/batch are int64

// ---------------- helpers ----------------------------------------------------
__device__ __forceinline__ float geluf(float x) {
    float t = tanhf(0.7978845608028654f * (x + 0.044715f * x * x * x));
    return 0.5f * x * (1.0f + t);
}
__device__ __forceinline__ float lrelu(float x) { return x > 0.f ? x : 0.2f * x; }

__device__ __forceinline__ long long load_idx(const void* p, long long i) {
    if (g_is64) return ((const long long*)p)[i];
    return (long long)((const int*)p)[i];
}

__device__ __forceinline__ unsigned f2tf32(float f) {
    unsigned r;
    asm("cvt.rna.tf32.f32 %0, %1;" : "=r"(r) : "f"(f));
    return r;
}
__device__ __forceinline__ void mma_tf32(float* c, const unsigned* a, const unsigned* b) {
    asm volatile(
        "mma.sync.aligned.m16n8k8.row.col.f32.tf32.tf32.f32 "
        "{%0,%1,%2,%3},{%4,%5,%6,%7},{%8,%9},{%0,%1,%2,%3};"
        : "+f"(c[0]), "+f"(c[1]), "+f"(c[2]), "+f"(c[3])
        : "r"(a[0]), "r"(a[1]), "r"(a[2]), "r"(a[3]), "r"(b[0]), "r"(b[1]));
}

// ---------------- dtype detection --------------------------------------------
__global__ void k_detect(const int* __restrict__ w32, int nwords) {
    __shared__ int nz;
    if (threadIdx.x == 0) nz = 0;
    __syncthreads();
    int pairs = nwords >> 1;
    int lim = min(pairs, 4096);
    for (int i = threadIdx.x; i < lim; i += blockDim.x)
        if (w32[2 * i + 1] != 0) nz = 1;
    __syncthreads();
    if (threadIdx.x == 0) g_is64 = (nz == 0) ? 1 : 0;
}

// ---------------- CSR construction -------------------------------------------
__global__ void k_zero_deg(int n) {
    int i = blockIdx.x * blockDim.x + threadIdx.x;
    if (i < n) g_deg[i] = 0;
}
__global__ void k_count(const void* __restrict__ ei, int E, int Etot, int n) {
    int e = blockIdx.x * blockDim.x + threadIdx.x;
    if (e >= Etot) return;
    int dst = (e < E) ? (int)load_idx(ei, (long long)E + e) : (e - E);
    if (dst >= 0 && dst < n) atomicAdd(&g_deg[dst], 1);
}
// 1024-thread two-level shuffle scan, 20-elem unrolled chunks
__global__ void __launch_bounds__(1024) k_scan(int n) {
    __shared__ int wsum[32];
    const int CH = 20;
    int t = threadIdx.x;
    int lane = t & 31, w = t >> 5;
    int b0 = t * CH;
    int vals[CH];
    int sum = 0;
    #pragma unroll
    for (int i = 0; i < CH; i++) {
        int idx = b0 + i;
        vals[i] = (idx < n) ? g_deg[idx] : 0;
        sum += vals[i];
    }
    int s = sum;
    #pragma unroll
    for (int off = 1; off < 32; off <<= 1) {
        int v = __shfl_up_sync(0xffffffffu, s, off);
        if (lane >= off) s += v;
    }
    if (lane == 31) wsum[w] = s;
    __syncthreads();
    if (w == 0) {
        int x = wsum[lane];
        #pragma unroll
        for (int off = 1; off < 32; off <<= 1) {
            int v = __shfl_up_sync(0xffffffffu, x, off);
            if (lane >= off) x += v;
        }
        wsum[lane] = x;
    }
    __syncthreads();
    int excl = s - sum + (w > 0 ? wsum[w - 1] : 0);
    int run = excl;
    #pragma unroll
    for (int i = 0; i < CH; i++) {
        int idx = b0 + i;
        if (idx < n) { g_row[idx] = run; g_cur[idx] = run; run += vals[i]; }
    }
    if (t == 0) g_row[n] = wsum[31];
}
__global__ void k_fill(const void* __restrict__ ei, int E, int Etot, int n) {
    int e = blockIdx.x * blockDim.x + threadIdx.x;
    if (e >= Etot) return;
    int src, dst;
    if (e < E) {
        src = (int)load_idx(ei, e);
        dst = (int)load_idx(ei, (long long)E + e);
    } else { src = e - E; dst = e - E; }
    if (dst < 0 || dst >= n || src < 0 || src >= n) return;
    int pos = atomicAdd(&g_cur[dst], 1);
    g_col[pos] = src;
    g_eid[pos] = e;
}

// ---------------- layer 1 (rank-1, 4 heads) ----------------------------------
__global__ void k_prep1(const float* __restrict__ W1, const float* __restrict__ as1,
                        const float* __restrict__ ad1) {
    __shared__ float ss[256], sd[256];
    int c = threadIdx.x;
    float w = W1[c];
    ss[c] = w * as1[c];
    sd[c] = w * ad1[c];
    __syncthreads();
    for (int off = 32; off; off >>= 1) {
        if ((c & 63) < off) { ss[c] += ss[c + off]; sd[c] += sd[c + off]; }
        __syncthreads();
    }
    if ((c & 63) == 0) { g_cs[c >> 6] = ss[c]; g_cd[c >> 6] = sd[c]; }
}
__global__ void k_sd1(const float* __restrict__ x, int n) {
    int i = blockIdx.x * blockDim.x + threadIdx.x;
    if (i >= n) return;
    float xv = x[i];
    #pragma unroll
    for (int h = 0; h < 4; h++) {
        g_as[i * 4 + h] = xv * g_cs[h];
        g_ad[i * 4 + h] = xv * g_cd[h];
    }
}
__global__ void k_att1(int n) {
    int w = (blockIdx.x * blockDim.x + threadIdx.x) >> 5;
    int lane = threadIdx.x & 31;
    if (w >= n) return;
    int b = g_row[w], e2 = g_row[w + 1];
    float4 ad = ((const float4*)g_ad)[w];
    float4 mx = make_float4(-1e30f, -1e30f, -1e30f, -1e30f);
    for (int p = b + lane; p < e2; p += 32) {
        float4 av = ((const float4*)g_as)[g_col[p]];
        float4 ev;
        ev.x = lrelu(av.x + ad.x); ev.y = lrelu(av.y + ad.y);
        ev.z = lrelu(av.z + ad.z); ev.w = lrelu(av.w + ad.w);
        ((float4*)g_ebuf)[p] = ev;
        mx.x = fmaxf(mx.x, ev.x); mx.y = fmaxf(mx.y, ev.y);
        mx.z = fmaxf(mx.z, ev.z); mx.w = fmaxf(mx.w, ev.w);
    }
    for (int o = 16; o; o >>= 1) {
        mx.x = fmaxf(mx.x, __shfl_xor_sync(0xffffffffu, mx.x, o));
        mx.y = fmaxf(mx.y, __shfl_xor_sync(0xffffffffu, mx.y, o));
        mx.z = fmaxf(mx.z, __shfl_xor_sync(0xffffffffu, mx.z, o));
        mx.w = fmaxf(mx.w, __shfl_xor_sync(0xffffffffu, mx.w, o));
    }
    float4 sm = make_float4(0, 0, 0, 0);
    for (int p = b + lane; p < e2; p += 32) {
        float4 ev = ((float4*)g_ebuf)[p];
        ev.x = expf(ev.x - mx.x); ev.y = expf(ev.y - mx.y);
        ev.z = expf(ev.z - mx.z); ev.w = expf(ev.w - mx.w);
        ((float4*)g_ebuf)[p] = ev;
        sm.x += ev.x; sm.y += ev.y; sm.z += ev.z; sm.w += ev.w;
    }
    for (int o = 16; o; o >>= 1) {
        sm.x += __shfl_xor_sync(0xffffffffu, sm.x, o);
        sm.y += __shfl_xor_sync(0xffffffffu, sm.y, o);
        sm.z += __shfl_xor_sync(0xffffffffu, sm.z, o);
        sm.w += __shfl_xor_sync(0xffffffffu, sm.w, o);
    }
    float4 inv;
    inv.x = 1.f / (sm.x + 1e-16f); inv.y = 1.f / (sm.y + 1e-16f);
    inv.z = 1.f / (sm.z + 1e-16f); inv.w = 1.f / (sm.w + 1e-16f);
    for (int p = b + lane; p < e2; p += 32) {
        float4 ev = ((float4*)g_ebuf)[p];
        ev.x *= inv.x; ev.y *= inv.y; ev.z *= inv.z; ev.w *= inv.w;
        ((float4*)g_ebuf)[p] = ev;
    }
}
__global__ void __launch_bounds__(256) k_agg1(const float* __restrict__ x,
                                              const float* __restrict__ W1,
                                              const float* __restrict__ b1, int n) {
    int d = blockIdx.x;
    if (d >= n) return;
    int tid = threadIdx.x;
    __shared__ float s4[4];
    if (tid < 32) {
        int b = g_row[d], e = g_row[d + 1];
        float4 acc = make_float4(0, 0, 0, 0);
        for (int p = b + tid; p < e; p += 32) {
            float4 al = ((const float4*)g_ebuf)[p];
            float xv = x[g_col[p]];
            acc.x += al.x * xv; acc.y += al.y * xv;
            acc.z += al.z * xv; acc.w += al.w * xv;
        }
        for (int o = 16; o; o >>= 1) {
            acc.x += __shfl_xor_sync(0xffffffffu, acc.x, o);
            acc.y += __shfl_xor_sync(0xffffffffu, acc.y, o);
            acc.z += __shfl_xor_sync(0xffffffffu, acc.z, o);
            acc.w += __shfl_xor_sync(0xffffffffu, acc.w, o);
        }
        if (tid == 0) { s4[0] = acc.x; s4[1] = acc.y; s4[2] = acc.z; s4[3] = acc.w; }
    }
    __syncthreads();
    g_X[d * 256 + tid] = geluf(s4[tid >> 6] * W1[tid] + b1[tid]);
}

// ---------------- tf32 tensor-core GEMM: g_H = g_X @ W  (M x 256 x 256) ------
// 128x64 block tile, BK=32, 8 warps (4m x 2n), warp tile 32x32 via m16n8k8.
__global__ void __launch_bounds__(256) k_gemm(const float* __restrict__ B, int M) {
    __shared__ unsigned As[32][136];   // tf32 bits, [k][m], bank = (8k+m)%32
    __shared__ unsigned Bs[32][72];    // tf32 bits, [k][n], bank = (8k+n)%32
    int tid = threadIdx.x;
    int lane = tid & 31;
    int wid = tid >> 5;
    int wm = (wid & 3) * 32;
    int wn = (wid >> 2) * 32;
    int m0 = blockIdx.x * 128;
    int n0 = blockIdx.y * 64;

    float acc[2][4][4];
    #pragma unroll
    for (int mi = 0; mi < 2; mi++)
        #pragma unroll
        for (int ni = 0; ni < 4; ni++)
            #pragma unroll
            for (int q = 0; q < 4; q++) acc[mi][ni][q] = 0.f;

    int am = tid & 31;            // A: m within 32-row pass
    int ak = 4 * (tid >> 5);      // A: k base (float4)
    int bn = 4 * (tid & 15);      // B: n base (float4)
    int bk = tid >> 4;            // B: k (passes k, k+16)

    for (int k0 = 0; k0 < 256; k0 += 32) {
        #pragma unroll
        for (int p = 0; p < 4; p++) {
            int gm = m0 + p * 32 + am;
            float4 v = make_float4(0, 0, 0, 0);
            if (gm < M) v = *(const float4*)&g_X[gm * 256 + k0 + ak];
            int sm_ = p * 32 + am;
            As[ak + 0][sm_] = f2tf32(v.x);
            As[ak + 1][sm_] = f2tf32(v.y);
            As[ak + 2][sm_] = f2tf32(v.z);
            As[ak + 3][sm_] = f2tf32(v.w);
        }
        #pragma unroll
        for (int p = 0; p < 2; p++) {
            int kk = bk + p * 16;
            float4 v = *(const float4*)&B[(k0 + kk) * 256 + n0 + bn];
            Bs[kk][bn + 0] = f2tf32(v.x);
            Bs[kk][bn + 1] = f2tf32(v.y);
            Bs[kk][bn + 2] = f2tf32(v.z);
            Bs[kk][bn + 3] = f2tf32(v.w);
        }
        __syncthreads();
        #pragma unroll
        for (int ks = 0; ks < 4; ks++) {
            int kb = ks * 8;
            int c4 = lane & 3, r8 = lane >> 2;
            unsigned a[2][4], bf[4][2];
            #pragma unroll
            for (int mi = 0; mi < 2; mi++) {
                int mr = wm + mi * 16 + r8;
                a[mi][0] = As[kb + c4][mr];
                a[mi][1] = As[kb + c4][mr + 8];
                a[mi][2] = As[kb + c4 + 4][mr];
                a[mi][3] = As[kb + c4 + 4][mr + 8];
            }
            #pragma unroll
            for (int ni = 0; ni < 4; ni++) {
                int nc = wn + ni * 8 + r8;
                bf[ni][0] = Bs[kb + c4][nc];
                bf[ni][1] = Bs[kb + c4 + 4][nc];
            }
            #pragma unroll
            for (int mi = 0; mi < 2; mi++)
                #pragma unroll
                for (int ni = 0; ni < 4; ni++)
                    mma_tf32(acc[mi][ni], a[mi], bf[ni]);
        }
        __syncthreads();
    }
    int r8 = lane >> 2, c4 = lane & 3;
    #pragma unroll
    for (int mi = 0; mi < 2; mi++) {
        int m = m0 + wm + mi * 16 + r8;
        #pragma unroll
        for (int ni = 0; ni < 4; ni++) {
            int nn = n0 + wn + ni * 8 + 2 * c4;
            if (m < M)
                *(float2*)&g_H[m * 256 + nn] =
                    make_float2(acc[mi][ni][0], acc[mi][ni][1]);
            if (m + 8 < M)
                *(float2*)&g_H[(m + 8) * 256 + nn] =
                    make_float2(acc[mi][ni][2], acc[mi][ni][3]);
        }
    }
}

// ---------------- per-node attention logits (layers 2-4) ---------------------
__global__ void k_sd(const float* __restrict__ av, const float* __restrict__ dv, int n) {
    int w = (blockIdx.x * blockDim.x + threadIdx.x) >> 5;
    int lane = threadIdx.x & 31;
    if (w >= n) return;
    const float4* h = (const float4*)(&g_H[w * 256]);
    float sa = 0.f, sd_ = 0.f;
    #pragma unroll
    for (int i = 0; i < 2; i++) {
        float4 hv = h[lane * 2 + i];
        float4 a = ((const float4*)av)[lane * 2 + i];
        float4 d = ((const float4*)dv)[lane * 2 + i];
        sa  += hv.x * a.x + hv.y * a.y + hv.z * a.z + hv.w * a.w;
        sd_ += hv.x * d.x + hv.y * d.y + hv.z * d.z + hv.w * d.w;
    }
    for (int o = 16; o; o >>= 1) {
        sa  += __shfl_xor_sync(0xffffffffu, sa, o);
        sd_ += __shfl_xor_sync(0xffffffffu, sd_, o);
    }
    if (lane == 0) { g_as[w] = sa; g_ad[w] = sd_; }
}

// ---------------- edge softmax (heads=1), warp per dst -----------------------
__global__ void k_att2(int n, float* alpha_out) {
    int d = (blockIdx.x * blockDim.x + threadIdx.x) >> 5;
    int lane = threadIdx.x & 31;
    if (d >= n) return;
    int b = g_row[d], e = g_row[d + 1];
    float ad = g_ad[d];
    float mx = -1e30f;
    for (int p = b + lane; p < e; p += 32) {
        float ev = lrelu(g_as[g_col[p]] + ad);
        g_ebuf[p] = ev;
        mx = fmaxf(mx, ev);
    }
    for (int o = 16; o; o >>= 1) mx = fmaxf(mx, __shfl_xor_sync(0xffffffffu, mx, o));
    float sm = 0.f;
    for (int p = b + lane; p < e; p += 32) {
        float ex = expf(g_ebuf[p] - mx);
        g_ebuf[p] = ex;
        sm += ex;
    }
    for (int o = 16; o; o >>= 1) sm += __shfl_xor_sync(0xffffffffu, sm, o);
    float inv = 1.f / (sm + 1e-16f);
    for (int p = b + lane; p < e; p += 32) {
        float al = g_ebuf[p] * inv;
        g_ebuf[p] = al;
        if (alpha_out) alpha_out[g_eid[p]] = al;
    }
}

// ---------------- aggregation: 64 threads/dst (float4/chan), 4 dst/block -----
__global__ void __launch_bounds__(256) k_agg2(const float* __restrict__ bias, int n) {
    int tid = threadIdx.x;
    int g = tid >> 6;            // group 0..3
    int c = tid & 63;            // float4 channel index
    int d = blockIdx.x * 4 + g;
    __shared__ float sal[4][32];
    __shared__ int   scol[4][32];
    __shared__ int   smx;
    int b = 0, e = 0;
    if (d < n) { b = g_row[d]; e = g_row[d + 1]; }
    int iters = (e - b + 31) >> 5;
    if (tid == 0) smx = 0;
    __syncthreads();
    if (c == 0) atomicMax(&smx, iters);
    __syncthreads();
    int MX = smx;
    float4 acc = make_float4(0, 0, 0, 0);
    for (int it = 0; it < MX; it++) {
        int base = b + it * 32;
        int lim = e - base;
        if (lim > 32) lim = 32;
        if (c < 32 && c < lim) { sal[g][c] = g_ebuf[base + c]; scol[g][c] = g_col[base + c]; }
        __syncthreads();
        for (int i = 0; i < lim; i++) {
            float4 h = *(const float4*)&g_H[scol[g][i] * 256 + c * 4];
            float a = sal[g][i];
            acc.x += a * h.x; acc.y += a * h.y; acc.z += a * h.z; acc.w += a * h.w;
        }
        __syncthreads();
    }
    if (d < n) {
        float4 bv = *(const float4*)&bias[c * 4];
        float4 o;
        o.x = geluf(acc.x + bv.x); o.y = geluf(acc.y + bv.y);
        o.z = geluf(acc.z + bv.z); o.w = geluf(acc.w + bv.w);
        *(float4*)&g_X[d * 256 + c * 4] = o;
    }
}

// ---------------- pooling + MLP -----------------------------------------------
__global__ void k_zero_pool() {
    int i = blockIdx.x * blockDim.x + threadIdx.x;
    if (i < NGRAPH * DD) g_gsum[i] = 0.f;
    if (i < NGRAPH) g_gcnt[i] = 0;
}
__global__ void k_gcnt(const void* __restrict__ batch, int n) {
    int i = blockIdx.x * blockDim.x + threadIdx.x;
    if (i < n) {
        int g = (int)load_idx(batch, i);
        if (g >= 0 && g < NGRAPH) atomicAdd(&g_gcnt[g], 1);
    }
}
__global__ void __launch_bounds__(256) k_pool(const void* __restrict__ batch, int n) {
    int n0 = blockIdx.x * 64;
    int c = threadIdx.x;
    if (n0 >= n) return;
    int g = (int)load_idx(batch, n0);
    float acc = 0.f;
    int lim = min(64, n - n0);
    for (int i = 0; i < lim; i++) {
        int node = n0 + i;
        int bg = (int)load_idx(batch, node);
        if (bg != g) { atomicAdd(&g_gsum[g * 256 + c], acc); acc = 0.f; g = bg; }
        acc += g_X[node * 256 + c];
    }
    atomicAdd(&g_gsum[g * 256 + c], acc);
}
__global__ void __launch_bounds__(512) k_mlp(const float* __restrict__ Wl1, const float* __restrict__ bl1,
                                             const float* __restrict__ Wl2, const float* __restrict__ bl2,
                                             const float* __restrict__ Wl3, const float* __restrict__ bl3,
                                             float* __restrict__ out) {
    __shared__ float G[16 * 256];
    __shared__ float G1[16 * 128];
    __shared__ float G2[16 * 64];
    int t = threadIdx.x;
    for (int i = t; i < 4096; i += 512) {
        int cnt = g_gcnt[i >> 8];
        G[i] = g_gsum[i] / (float)(cnt > 0 ? cnt : 1);
    }
    __syncthreads();
    for (int i = t; i < 2048; i += 512) {
        int gi = i >> 7, j = i & 127;
        float a = bl1[j];
        for (int k = 0; k < 256; k++) a += G[gi * 256 + k] * Wl1[k * 128 + j];
        G1[i] = geluf(a);
    }
    __syncthreads();
    for (int i = t; i < 1024; i += 512) {
        int gi = i >> 6, j = i & 63;
        float a = bl2[j];
        for (int k = 0; k < 128; k++) a += G1[gi * 128 + k] * Wl2[k * 64 + j];
        G2[i] = geluf(a);
    }
    __syncthreads();
    if (t < 16) {
        float a = bl3[0];
        for (int k = 0; k < 64; k++) a += G2[t * 64 + k] * Wl3[k];
        out[t] = 1.f / (1.f + expf(-a));
    }
}

// ---------------- attn_edge_index output --------------------------------------
__global__ void k_attn_idx(const void* __restrict__ ei, int E, int Etot,
                           float* __restrict__ dst) {
    int i = blockIdx.x * blockDim.x + threadIdx.x;
    if (i >= 2 * Etot) return;
    int which = i / Etot;        // 0 = src row, 1 = dst row
    int e = i - which * Etot;
    long long v = (e < E) ? load_idx(ei, (long long)which * E + e)
                          : (long long)(e - E);
    dst[i] = (float)v;
}

// ---------------- host launcher ------------------------------------------------
extern "C" void kernel_launch(void* const* d_in, const int* in_sizes, int n_in,
                              void* d_out, int out_size) {
    const float* x     = (const float*)d_in[0];
    const void*  ei    = d_in[1];
    const void*  batch = d_in[2];
    const float* W1  = (const float*)d_in[3];
    const float* as1 = (const float*)d_in[4];
    const float* ad1 = (const float*)d_in[5];
    const float* b1  = (const float*)d_in[6];
    const float* W2  = (const float*)d_in[7];
    const float* as2 = (const float*)d_in[8];
    const float* ad2 = (const float*)d_in[9];
    const float* b2  = (const float*)d_in[10];
    const float* Wl1 = (const float*)d_in[11];
    const float* bl1 = (const float*)d_in[12];
    const float* Wl2 = (const float*)d_in[13];
    const float* bl2 = (const float*)d_in[14];
    const float* Wl3 = (const float*)d_in[15];
    const float* bl3 = (const float*)d_in[16];

    int Nn = in_sizes[0];          // nodes (x is [N,1])
    int E = in_sizes[1] / 2;       // edges
    int Etot = E + Nn;             // with self-loops
    float* out = (float*)d_out;
    bool full = (out_size >= 16 + 3 * Etot);
    float* alpha_out = full ? (out + 16 + 2 * Etot) : nullptr;

    // ---- dtype detection (int32 vs int64 edge/batch arrays) ----
    k_detect<<<1, 256>>>((const int*)ei, 2 * E);

    // ---- CSR (counting sort by dst) ----
    k_zero_deg<<<(Nn + 255) / 256, 256>>>(Nn);
    k_count<<<(Etot + 255) / 256, 256>>>(ei, E, Etot, Nn);
    k_scan<<<1, 1024>>>(Nn);
    k_fill<<<(Etot + 255) / 256, 256>>>(ei, E, Etot, Nn);

    // ---- layer 1 (GATConv(1, 64, heads=4), rank-1 collapse) ----
    k_prep1<<<1, 256>>>(W1, as1, ad1);
    k_sd1<<<(Nn + 255) / 256, 256>>>(x, Nn);
    k_att1<<<(Nn + 7) / 8, 256>>>(Nn);
    k_agg1<<<Nn, 256>>>(x, W1, b1, Nn);

    // ---- layers 2-4 (GATConv(256, 256, heads=1)) ----
    for (int l = 0; l < 3; l++) {
        k_gemm<<<dim3((Nn + 127) / 128, 4), 256>>>(W2 + l * 65536, Nn);
        k_sd<<<(Nn + 7) / 8, 256>>>(as2 + l * 256, ad2 + l * 256, Nn);
        k_att2<<<(Nn + 7) / 8, 256>>>(Nn, (l == 2) ? alpha_out : nullptr);
        k_agg2<<<(Nn + 3) / 4, 256>>>(b2 + l * 256, Nn);
    }

    // ---- mean pool + MLP head ----
    k_zero_pool<<<17, 256>>>();
    k_gcnt<<<(Nn + 255) / 256, 256>>>(batch, Nn);
    k_pool<<<(Nn + 63) / 64, 256>>>(batch, Nn);
    k_mlp<<<1, 512>>>(Wl1, bl1, Wl2, bl2, Wl3, bl3, out);

    // ---- attn_edge_index output ----
    if (full) k_attn_idx<<<(2 * Etot + 255) / 256, 256>>>(ei, E, Etot, out + 16);
}

// round 4
// speedup vs baseline: 1.3832x; 1.0549x over previous
#include <cuda_runtime.h>
#include <math.h>

#define NMAX   20000
#define ETOT_MAX 340000
#define DD     256
#define NGRAPH 16

// ---------------- scratch (static device globals; no allocation) -------------
__device__ float g_X[NMAX * DD];        // current features (layer input/output)
__device__ float g_H[NMAX * DD];        // post-GEMM transformed features
__device__ float g_ebuf[ETOT_MAX * 4];  // per-edge e/exp/alpha scratch (4 heads L1)
__device__ float g_as[NMAX * 4];        // per-node source attention logits
__device__ float g_ad[NMAX * 4];        // per-node dest   attention logits
__device__ int   g_deg[NMAX];
__device__ int   g_row[NMAX + 1];
__device__ int   g_cur[NMAX];
__device__ int   g_col[ETOT_MAX];       // src node per CSR slot
__device__ int   g_eid[ETOT_MAX];       // original edge id per CSR slot
__device__ float g_cs[4], g_cd[4];      // layer-1 collapsed attention weights
__device__ float g_gsum[NGRAPH * DD];
__device__ int   g_gcnt[NGRAPH];
__device__ int   g_is64;                // 1 if edge_index/batch are int64

// ---------------- helpers ----------------------------------------------------
__device__ __forceinline__ float geluf(float x) {
    float t = tanhf(0.7978845608028654f * (x + 0.044715f * x * x * x));
    return 0.5f * x * (1.0f + t);
}
__device__ __forceinline__ float lrelu(float x) { return x > 0.f ? x : 0.2f * x; }

__device__ __forceinline__ long long load_idx(const void* p, long long i) {
    if (g_is64) return ((const long long*)p)[i];
    return (long long)((const int*)p)[i];
}

__device__ __forceinline__ unsigned f2tf32(float f) {
    unsigned r;
    asm("cvt.rna.tf32.f32 %0, %1;" : "=r"(r) : "f"(f));
    return r;
}
__device__ __forceinline__ void mma_tf32(float* c, const unsigned* a, const unsigned* b) {
    asm volatile(
        "mma.sync.aligned.m16n8k8.row.col.f32.tf32.tf32.f32 "
        "{%0,%1,%2,%3},{%4,%5,%6,%7},{%8,%9},{%0,%1,%2,%3};"
        : "+f"(c[0]), "+f"(c[1]), "+f"(c[2]), "+f"(c[3])
        : "r"(a[0]), "r"(a[1]), "r"(a[2]), "r"(a[3]), "r"(b[0]), "r"(b[1]));
}

// ---------------- dtype detection --------------------------------------------
__global__ void k_detect(const int* __restrict__ w32, int nwords) {
    __shared__ int nz;
    if (threadIdx.x == 0) nz = 0;
    __syncthreads();
    int pairs = nwords >> 1;
    int lim = min(pairs, 4096);
    for (int i = threadIdx.x; i < lim; i += blockDim.x)
        if (w32[2 * i + 1] != 0) nz = 1;
    __syncthreads();
    if (threadIdx.x == 0) g_is64 = (nz == 0) ? 1 : 0;
}

// ---------------- CSR construction (+ pool zeroing folded in) ----------------
__global__ void k_zero_deg(int n) {
    int i = blockIdx.x * blockDim.x + threadIdx.x;
    if (i < n) g_deg[i] = 0;
    if (i < NGRAPH * DD) g_gsum[i] = 0.f;
    if (i < NGRAPH) g_gcnt[i] = 0;
}
__global__ void k_count(const void* __restrict__ ei, int E, int Etot, int n) {
    int e = blockIdx.x * blockDim.x + threadIdx.x;
    if (e >= Etot) return;
    int dst = (e < E) ? (int)load_idx(ei, (long long)E + e) : (e - E);
    if (dst >= 0 && dst < n) atomicAdd(&g_deg[dst], 1);
}
// coalesced two-phase scan: stage 10240 elems through smem per phase
__global__ void __launch_bounds__(1024) k_scan(int n) {
    __shared__ int sbuf[10240];
    __shared__ int wsum[32];
    int t = threadIdx.x, lane = t & 31, w = t >> 5;
    int carry = 0;
    #pragma unroll
    for (int ph = 0; ph < 2; ph++) {
        int base = ph * 10240;
        #pragma unroll
        for (int j = 0; j < 10; j++) {
            int idx = base + j * 1024 + t;
            sbuf[j * 1024 + t] = (idx < n) ? g_deg[idx] : 0;
        }
        __syncthreads();
        int vals[10], sum = 0;
        #pragma unroll
        for (int i = 0; i < 10; i++) { vals[i] = sbuf[t * 10 + i]; sum += vals[i]; }
        int s = sum;
        #pragma unroll
        for (int off = 1; off < 32; off <<= 1) {
            int v = __shfl_up_sync(0xffffffffu, s, off);
            if (lane >= off) s += v;
        }
        if (lane == 31) wsum[w] = s;
        __syncthreads();
        if (w == 0) {
            int x = wsum[lane];
            #pragma unroll
            for (int off = 1; off < 32; off <<= 1) {
                int v = __shfl_up_sync(0xffffffffu, x, off);
                if (lane >= off) x += v;
            }
            wsum[lane] = x;
        }
        __syncthreads();
        int excl = s - sum + (w > 0 ? wsum[w - 1] : 0) + carry;
        int total = wsum[31];
        __syncthreads();
        int run = excl;
        #pragma unroll
        for (int i = 0; i < 10; i++) { sbuf[t * 10 + i] = run; run += vals[i]; }
        __syncthreads();
        #pragma unroll
        for (int j = 0; j < 10; j++) {
            int idx = base + j * 1024 + t;
            if (idx < n) { int v = sbuf[j * 1024 + t]; g_row[idx] = v; g_cur[idx] = v; }
        }
        carry += total;
        __syncthreads();
    }
    if (t == 0) g_row[n] = carry;
}
__global__ void k_fill(const void* __restrict__ ei, int E, int Etot, int n) {
    int e = blockIdx.x * blockDim.x + threadIdx.x;
    if (e >= Etot) return;
    int src, dst;
    if (e < E) {
        src = (int)load_idx(ei, e);
        dst = (int)load_idx(ei, (long long)E + e);
    } else { src = e - E; dst = e - E; }
    if (dst < 0 || dst >= n || src < 0 || src >= n) return;
    int pos = atomicAdd(&g_cur[dst], 1);
    g_col[pos] = src;
    g_eid[pos] = e;
}

// ---------------- layer 1 (rank-1, 4 heads) ----------------------------------
__global__ void k_prep1(const float* __restrict__ W1, const float* __restrict__ as1,
                        const float* __restrict__ ad1) {
    __shared__ float ss[256], sd[256];
    int c = threadIdx.x;
    float w = W1[c];
    ss[c] = w * as1[c];
    sd[c] = w * ad1[c];
    __syncthreads();
    for (int off = 32; off; off >>= 1) {
        if ((c & 63) < off) { ss[c] += ss[c + off]; sd[c] += sd[c + off]; }
        __syncthreads();
    }
    if ((c & 63) == 0) { g_cs[c >> 6] = ss[c]; g_cd[c >> 6] = sd[c]; }
}
// per-node 4-head logits + graph-count atomics (gcnt folded in)
__global__ void k_sd1(const float* __restrict__ x, const void* __restrict__ batch, int n) {
    int i = blockIdx.x * blockDim.x + threadIdx.x;
    if (i >= n) return;
    float xv = x[i];
    #pragma unroll
    for (int h = 0; h < 4; h++) {
        g_as[i * 4 + h] = xv * g_cs[h];
        g_ad[i * 4 + h] = xv * g_cd[h];
    }
    int g = (int)load_idx(batch, i);
    if (g >= 0 && g < NGRAPH) atomicAdd(&g_gcnt[g], 1);
}
__global__ void k_att1(int n) {
    int w = (blockIdx.x * blockDim.x + threadIdx.x) >> 5;
    int lane = threadIdx.x & 31;
    if (w >= n) return;
    int b = g_row[w], e2 = g_row[w + 1];
    float4 ad = ((const float4*)g_ad)[w];
    float4 mx = make_float4(-1e30f, -1e30f, -1e30f, -1e30f);
    for (int p = b + lane; p < e2; p += 32) {
        float4 av = ((const float4*)g_as)[g_col[p]];
        float4 ev;
        ev.x = lrelu(av.x + ad.x); ev.y = lrelu(av.y + ad.y);
        ev.z = lrelu(av.z + ad.z); ev.w = lrelu(av.w + ad.w);
        ((float4*)g_ebuf)[p] = ev;
        mx.x = fmaxf(mx.x, ev.x); mx.y = fmaxf(mx.y, ev.y);
        mx.z = fmaxf(mx.z, ev.z); mx.w = fmaxf(mx.w, ev.w);
    }
    for (int o = 16; o; o >>= 1) {
        mx.x = fmaxf(mx.x, __shfl_xor_sync(0xffffffffu, mx.x, o));
        mx.y = fmaxf(mx.y, __shfl_xor_sync(0xffffffffu, mx.y, o));
        mx.z = fmaxf(mx.z, __shfl_xor_sync(0xffffffffu, mx.z, o));
        mx.w = fmaxf(mx.w, __shfl_xor_sync(0xffffffffu, mx.w, o));
    }
    float4 sm = make_float4(0, 0, 0, 0);
    for (int p = b + lane; p < e2; p += 32) {
        float4 ev = ((float4*)g_ebuf)[p];
        ev.x = expf(ev.x - mx.x); ev.y = expf(ev.y - mx.y);
        ev.z = expf(ev.z - mx.z); ev.w = expf(ev.w - mx.w);
        ((float4*)g_ebuf)[p] = ev;
        sm.x += ev.x; sm.y += ev.y; sm.z += ev.z; sm.w += ev.w;
    }
    for (int o = 16; o; o >>= 1) {
        sm.x += __shfl_xor_sync(0xffffffffu, sm.x, o);
        sm.y += __shfl_xor_sync(0xffffffffu, sm.y, o);
        sm.z += __shfl_xor_sync(0xffffffffu, sm.z, o);
        sm.w += __shfl_xor_sync(0xffffffffu, sm.w, o);
    }
    float4 inv;
    inv.x = 1.f / (sm.x + 1e-16f); inv.y = 1.f / (sm.y + 1e-16f);
    inv.z = 1.f / (sm.z + 1e-16f); inv.w = 1.f / (sm.w + 1e-16f);
    for (int p = b + lane; p < e2; p += 32) {
        float4 ev = ((float4*)g_ebuf)[p];
        ev.x *= inv.x; ev.y *= inv.y; ev.z *= inv.z; ev.w *= inv.w;
        ((float4*)g_ebuf)[p] = ev;
    }
}
__global__ void __launch_bounds__(256) k_agg1(const float* __restrict__ x,
                                              const float* __restrict__ W1,
                                              const float* __restrict__ b1, int n) {
    int d = blockIdx.x;
    if (d >= n) return;
    int tid = threadIdx.x;
    __shared__ float s4[4];
    if (tid < 32) {
        int b = g_row[d], e = g_row[d + 1];
        float4 acc = make_float4(0, 0, 0, 0);
        for (int p = b + tid; p < e; p += 32) {
            float4 al = ((const float4*)g_ebuf)[p];
            float xv = x[g_col[p]];
            acc.x += al.x * xv; acc.y += al.y * xv;
            acc.z += al.z * xv; acc.w += al.w * xv;
        }
        for (int o = 16; o; o >>= 1) {
            acc.x += __shfl_xor_sync(0xffffffffu, acc.x, o);
            acc.y += __shfl_xor_sync(0xffffffffu, acc.y, o);
            acc.z += __shfl_xor_sync(0xffffffffu, acc.z, o);
            acc.w += __shfl_xor_sync(0xffffffffu, acc.w, o);
        }
        if (tid == 0) { s4[0] = acc.x; s4[1] = acc.y; s4[2] = acc.z; s4[3] = acc.w; }
    }
    __syncthreads();
    g_X[d * 256 + tid] = geluf(s4[tid >> 6] * W1[tid] + b1[tid]);
    // zero single-head logits for the fused GEMM epilogue atomics
    if (tid == 0) { g_as[d] = 0.f; g_ad[d] = 0.f; }
}

// ---------------- tf32 TC GEMM + fused a_s/a_d epilogue ----------------------
// g_H = g_X @ W; also atomically accumulates g_as/g_ad = g_H @ att_{s,d}.
// 128x64 block tile, BK=32, 8 warps (4m x 2n), register-prefetch double buffer.
__global__ void __launch_bounds__(256) k_gemm(const float* __restrict__ B,
                                              const float* __restrict__ att_s,
                                              const float* __restrict__ att_d, int M) {
    __shared__ unsigned As[32][136];   // tf32 bits, [k][m]
    __shared__ unsigned Bs[32][72];    // tf32 bits, [k][n]
    int tid = threadIdx.x;
    int lane = tid & 31;
    int wid = tid >> 5;
    int wm = (wid & 3) * 32;
    int wn = (wid >> 2) * 32;
    int m0 = blockIdx.x * 128;
    int n0 = blockIdx.y * 64;

    float acc[2][4][4];
    #pragma unroll
    for (int mi = 0; mi < 2; mi++)
        #pragma unroll
        for (int ni = 0; ni < 4; ni++)
            #pragma unroll
            for (int q = 0; q < 4; q++) acc[mi][ni][q] = 0.f;

    int am = tid & 31;            // A: m within 32-row pass
    int ak = 4 * (tid >> 5);      // A: k base (float4)
    int bn = 4 * (tid & 15);      // B: n base (float4)
    int bk = tid >> 4;            // B: k (passes k, k+16)

    float4 va[4], vb[2];
    // prologue load k0=0
    #pragma unroll
    for (int p = 0; p < 4; p++) {
        int gm = m0 + p * 32 + am;
        va[p] = make_float4(0, 0, 0, 0);
        if (gm < M) va[p] = *(const float4*)&g_X[gm * 256 + ak];
    }
    #pragma unroll
    for (int p = 0; p < 2; p++)
        vb[p] = *(const float4*)&B[(bk + p * 16) * 256 + n0 + bn];

    for (int k0 = 0; k0 < 256; k0 += 32) {
        // stage current tile to smem (tf32 convert at store)
        #pragma unroll
        for (int p = 0; p < 4; p++) {
            int sm_ = p * 32 + am;
            As[ak + 0][sm_] = f2tf32(va[p].x);
            As[ak + 1][sm_] = f2tf32(va[p].y);
            As[ak + 2][sm_] = f2tf32(va[p].z);
            As[ak + 3][sm_] = f2tf32(va[p].w);
        }
        #pragma unroll
        for (int p = 0; p < 2; p++) {
            int kk = bk + p * 16;
            Bs[kk][bn + 0] = f2tf32(vb[p].x);
            Bs[kk][bn + 1] = f2tf32(vb[p].y);
            Bs[kk][bn + 2] = f2tf32(vb[p].z);
            Bs[kk][bn + 3] = f2tf32(vb[p].w);
        }
        __syncthreads();
        // prefetch next tile while computing this one
        if (k0 + 32 < 256) {
            int kn = k0 + 32;
            #pragma unroll
            for (int p = 0; p < 4; p++) {
                int gm = m0 + p * 32 + am;
                va[p] = make_float4(0, 0, 0, 0);
                if (gm < M) va[p] = *(const float4*)&g_X[gm * 256 + kn + ak];
            }
            #pragma unroll
            for (int p = 0; p < 2; p++)
                vb[p] = *(const float4*)&B[(kn + bk + p * 16) * 256 + n0 + bn];
        }
        #pragma unroll
        for (int ks = 0; ks < 4; ks++) {
            int kb = ks * 8;
            int c4 = lane & 3, r8 = lane >> 2;
            unsigned a[2][4], bf[4][2];
            #pragma unroll
            for (int mi = 0; mi < 2; mi++) {
                int mr = wm + mi * 16 + r8;
                a[mi][0] = As[kb + c4][mr];
                a[mi][1] = As[kb + c4][mr + 8];
                a[mi][2] = As[kb + c4 + 4][mr];
                a[mi][3] = As[kb + c4 + 4][mr + 8];
            }
            #pragma unroll
            for (int ni = 0; ni < 4; ni++) {
                int nc = wn + ni * 8 + r8;
                bf[ni][0] = Bs[kb + c4][nc];
                bf[ni][1] = Bs[kb + c4 + 4][nc];
            }
            #pragma unroll
            for (int mi = 0; mi < 2; mi++)
                #pragma unroll
                for (int ni = 0; ni < 4; ni++)
                    mma_tf32(acc[mi][ni], a[mi], bf[ni]);
        }
        __syncthreads();
    }
    int r8 = lane >> 2, c4 = lane & 3;
    // store H tile + accumulate per-row attention partials
    float pas[4] = {0, 0, 0, 0}, pad_[4] = {0, 0, 0, 0};
    #pragma unroll
    for (int mi = 0; mi < 2; mi++) {
        int m = m0 + wm + mi * 16 + r8;
        #pragma unroll
        for (int ni = 0; ni < 4; ni++) {
            int nn = n0 + wn + ni * 8 + 2 * c4;
            float s0 = __ldg(&att_s[nn]), s1 = __ldg(&att_s[nn + 1]);
            float d0 = __ldg(&att_d[nn]), d1 = __ldg(&att_d[nn + 1]);
            pas[2 * mi]     += acc[mi][ni][0] * s0 + acc[mi][ni][1] * s1;
            pas[2 * mi + 1] += acc[mi][ni][2] * s0 + acc[mi][ni][3] * s1;
            pad_[2 * mi]     += acc[mi][ni][0] * d0 + acc[mi][ni][1] * d1;
            pad_[2 * mi + 1] += acc[mi][ni][2] * d0 + acc[mi][ni][3] * d1;
            if (m < M)
                *(float2*)&g_H[m * 256 + nn] =
                    make_float2(acc[mi][ni][0], acc[mi][ni][1]);
            if (m + 8 < M)
                *(float2*)&g_H[(m + 8) * 256 + nn] =
                    make_float2(acc[mi][ni][2], acc[mi][ni][3]);
        }
    }
    // reduce across the 4 lanes sharing r8 (lane = r8*4 + c4)
    #pragma unroll
    for (int off = 1; off < 4; off <<= 1) {
        #pragma unroll
        for (int r = 0; r < 4; r++) {
            pas[r]  += __shfl_xor_sync(0xffffffffu, pas[r], off);
            pad_[r] += __shfl_xor_sync(0xffffffffu, pad_[r], off);
        }
    }
    if (c4 == 0) {
        #pragma unroll
        for (int r = 0; r < 4; r++) {
            int row = wm + r8 + (r & 1) * 8 + (r >> 1) * 16;
            int m = m0 + row;
            if (m < M) {
                atomicAdd(&g_as[m], pas[r]);
                atomicAdd(&g_ad[m], pad_[r]);
            }
        }
    }
}

// ---------------- edge softmax (heads=1), warp per dst -----------------------
__global__ void k_att2(int n, float* alpha_out) {
    int d = (blockIdx.x * blockDim.x + threadIdx.x) >> 5;
    int lane = threadIdx.x & 31;
    if (d >= n) return;
    int b = g_row[d], e = g_row[d + 1];
    float ad = g_ad[d];
    float mx = -1e30f;
    for (int p = b + lane; p < e; p += 32) {
        float ev = lrelu(g_as[g_col[p]] + ad);
        g_ebuf[p] = ev;
        mx = fmaxf(mx, ev);
    }
    for (int o = 16; o; o >>= 1) mx = fmaxf(mx, __shfl_xor_sync(0xffffffffu, mx, o));
    float sm = 0.f;
    for (int p = b + lane; p < e; p += 32) {
        float ex = expf(g_ebuf[p] - mx);
        g_ebuf[p] = ex;
        sm += ex;
    }
    for (int o = 16; o; o >>= 1) sm += __shfl_xor_sync(0xffffffffu, sm, o);
    float inv = 1.f / (sm + 1e-16f);
    for (int p = b + lane; p < e; p += 32) {
        float al = g_ebuf[p] * inv;
        g_ebuf[p] = al;
        if (alpha_out) alpha_out[g_eid[p]] = al;
    }
}

// ---------------- aggregation: 64 threads/dst (float4/chan), 4 dst/block -----
__global__ void __launch_bounds__(256) k_agg2(const float* __restrict__ bias, int n) {
    int tid = threadIdx.x;
    int g = tid >> 6;            // group 0..3
    int c = tid & 63;            // float4 channel index
    int d = blockIdx.x * 4 + g;
    __shared__ float sal[4][32];
    __shared__ int   scol[4][32];
    __shared__ int   smx;
    int b = 0, e = 0;
    if (d < n) { b = g_row[d]; e = g_row[d + 1]; }
    int iters = (e - b + 31) >> 5;
    if (tid == 0) smx = 0;
    __syncthreads();
    if (c == 0) atomicMax(&smx, iters);
    __syncthreads();
    int MX = smx;
    float4 acc = make_float4(0, 0, 0, 0);
    for (int it = 0; it < MX; it++) {
        int base = b + it * 32;
        int lim = e - base;
        if (lim > 32) lim = 32;
        if (c < 32 && c < lim) { sal[g][c] = g_ebuf[base + c]; scol[g][c] = g_col[base + c]; }
        __syncthreads();
        for (int i = 0; i < lim; i++) {
            float4 h = *(const float4*)&g_H[scol[g][i] * 256 + c * 4];
            float a = sal[g][i];
            acc.x += a * h.x; acc.y += a * h.y; acc.z += a * h.z; acc.w += a * h.w;
        }
        __syncthreads();
    }
    if (d < n) {
        float4 bv = *(const float4*)&bias[c * 4];
        float4 o;
        o.x = geluf(acc.x + bv.x); o.y = geluf(acc.y + bv.y);
        o.z = geluf(acc.z + bv.z); o.w = geluf(acc.w + bv.w);
        *(float4*)&g_X[d * 256 + c * 4] = o;
        if (c == 0) { g_as[d] = 0.f; g_ad[d] = 0.f; }   // reset for next layer's epilogue
    }
}

// ---------------- pooling + MLP -----------------------------------------------
__global__ void __launch_bounds__(256) k_pool(const void* __restrict__ batch, int n) {
    int n0 = blockIdx.x * 64;
    int c = threadIdx.x;
    if (n0 >= n) return;
    int g = (int)load_idx(batch, n0);
    float acc = 0.f;
    int lim = min(64, n - n0);
    for (int i = 0; i < lim; i++) {
        int node = n0 + i;
        int bg = (int)load_idx(batch, node);
        if (bg != g) { atomicAdd(&g_gsum[g * 256 + c], acc); acc = 0.f; g = bg; }
        acc += g_X[node * 256 + c];
    }
    atomicAdd(&g_gsum[g * 256 + c], acc);
}
__global__ void __launch_bounds__(512) k_mlp(const float* __restrict__ Wl1, const float* __restrict__ bl1,
                                             const float* __restrict__ Wl2, const float* __restrict__ bl2,
                                             const float* __restrict__ Wl3, const float* __restrict__ bl3,
                                             float* __restrict__ out) {
    __shared__ float G[16 * 256];
    __shared__ float G1[16 * 128];
    __shared__ float G2[16 * 64];
    int t = threadIdx.x;
    for (int i = t; i < 4096; i += 512) {
        int cnt = g_gcnt[i >> 8];
        G[i] = g_gsum[i] / (float)(cnt > 0 ? cnt : 1);
    }
    __syncthreads();
    for (int i = t; i < 2048; i += 512) {
        int gi = i >> 7, j = i & 127;
        float a = bl1[j];
        for (int k = 0; k < 256; k++) a += G[gi * 256 + k] * Wl1[k * 128 + j];
        G1[i] = geluf(a);
    }
    __syncthreads();
    for (int i = t; i < 1024; i += 512) {
        int gi = i >> 6, j = i & 63;
        float a = bl2[j];
        for (int k = 0; k < 128; k++) a += G1[gi * 128 + k] * Wl2[k * 64 + j];
        G2[i] = geluf(a);
    }
    __syncthreads();
    if (t < 16) {
        float a = bl3[0];
        for (int k = 0; k < 64; k++) a += G2[t * 64 + k] * Wl3[k];
        out[t] = 1.f / (1.f + expf(-a));
    }
}

// ---------------- attn_edge_index output --------------------------------------
__global__ void k_attn_idx(const void* __restrict__ ei, int E, int Etot,
                           float* __restrict__ dst) {
    int i = blockIdx.x * blockDim.x + threadIdx.x;
    if (i >= 2 * Etot) return;
    int which = i / Etot;        // 0 = src row, 1 = dst row
    int e = i - which * Etot;
    long long v = (e < E) ? load_idx(ei, (long long)which * E + e)
                          : (long long)(e - E);
    dst[i] = (float)v;
}

// ---------------- host launcher ------------------------------------------------
extern "C" void kernel_launch(void* const* d_in, const int* in_sizes, int n_in,
                              void* d_out, int out_size) {
    const float* x     = (const float*)d_in[0];
    const void*  ei    = d_in[1];
    const void*  batch = d_in[2];
    const float* W1  = (const float*)d_in[3];
    const float* as1 = (const float*)d_in[4];
    const float* ad1 = (const float*)d_in[5];
    const float* b1  = (const float*)d_in[6];
    const float* W2  = (const float*)d_in[7];
    const float* as2 = (const float*)d_in[8];
    const float* ad2 = (const float*)d_in[9];
    const float* b2  = (const float*)d_in[10];
    const float* Wl1 = (const float*)d_in[11];
    const float* bl1 = (const float*)d_in[12];
    const float* Wl2 = (const float*)d_in[13];
    const float* bl2 = (const float*)d_in[14];
    const float* Wl3 = (const float*)d_in[15];
    const float* bl3 = (const float*)d_in[16];

    int Nn = in_sizes[0];          // nodes (x is [N,1])
    int E = in_sizes[1] / 2;       // edges
    int Etot = E + Nn;             // with self-loops
    float* out = (float*)d_out;
    bool full = (out_size >= 16 + 3 * Etot);
    float* alpha_out = full ? (out + 16 + 2 * Etot) : nullptr;

    // ---- dtype detection (int32 vs int64 edge/batch arrays) ----
    k_detect<<<1, 256>>>((const int*)ei, 2 * E);

    // ---- CSR (counting sort by dst); also zeros pool arrays ----
    k_zero_deg<<<(Nn + 255) / 256, 256>>>(Nn);
    k_count<<<(Etot + 255) / 256, 256>>>(ei, E, Etot, Nn);
    k_scan<<<1, 1024>>>(Nn);
    k_fill<<<(Etot + 255) / 256, 256>>>(ei, E, Etot, Nn);

    // ---- layer 1 (GATConv(1, 64, heads=4), rank-1 collapse) ----
    k_prep1<<<1, 256>>>(W1, as1, ad1);
    k_sd1<<<(Nn + 255) / 256, 256>>>(x, batch, Nn);
    k_att1<<<(Nn + 7) / 8, 256>>>(Nn);
    k_agg1<<<Nn, 256>>>(x, W1, b1, Nn);

    // ---- layers 2-4 (GATConv(256, 256, heads=1)) ----
    for (int l = 0; l < 3; l++) {
        k_gemm<<<dim3((Nn + 127) / 128, 4), 256>>>(W2 + l * 65536,
                                                   as2 + l * 256, ad2 + l * 256, Nn);
        k_att2<<<(Nn + 7) / 8, 256>>>(Nn, (l == 2) ? alpha_out : nullptr);
        k_agg2<<<(Nn + 3) / 4, 256>>>(b2 + l * 256, Nn);
    }

    // ---- mean pool + MLP head ----
    k_pool<<<(Nn + 63) / 64, 256>>>(batch, Nn);
    k_mlp<<<1, 512>>>(Wl1, bl1, Wl2, bl2, Wl3, bl3, out);

    // ---- attn_edge_index output ----
    if (full) k_attn_idx<<<(2 * Etot + 255) / 256, 256>>>(ei, E, Etot, out + 16);
}

// round 5
// speedup vs baseline: 1.4323x; 1.0355x over previous
#include <cuda_runtime.h>
#include <cuda_bf16.h>
#include <math.h>

#define NMAX   20000
#define ETOT_MAX 340000
#define DD     256
#define NGRAPH 16

// ---------------- scratch (static device globals; no allocation) -------------
__device__ float    g_X[NMAX * DD];      // current features (layer input/output)
__device__ unsigned g_Hb[NMAX * 128];    // post-GEMM features, bf16x2 packed
__device__ float    g_ebuf[ETOT_MAX * 4];// per-edge scratch (4 heads L1)
__device__ float    g_as[NMAX * 4];      // per-node source attention logits
__device__ float    g_ad[NMAX * 4];      // per-node dest   attention logits
__device__ int      g_deg[NMAX];
__device__ int      g_row[NMAX + 1];
__device__ int      g_cur[NMAX];
__device__ int      g_col[ETOT_MAX];     // src node per CSR slot
__device__ int      g_eid[ETOT_MAX];     // original edge id per CSR slot
__device__ float    g_cs[4], g_cd[4];    // layer-1 collapsed attention weights
__device__ float    g_gsum[NGRAPH * DD];
__device__ int      g_goff[NGRAPH + 1];  // graph node-range boundaries (sorted batch)
__device__ int      g_is64;              // 1 if edge_index/batch are int64

// ---------------- helpers ----------------------------------------------------
__device__ __forceinline__ float geluf(float x) {
    float t = tanhf(0.7978845608028654f * (x + 0.044715f * x * x * x));
    return 0.5f * x * (1.0f + t);
}
__device__ __forceinline__ float lrelu(float x) { return x > 0.f ? x : 0.2f * x; }

__device__ __forceinline__ long long load_idx(const void* p, long long i) {
    if (g_is64) return ((const long long*)p)[i];
    return (long long)((const int*)p)[i];
}

__device__ __forceinline__ unsigned f2tf32(float f) {
    unsigned r;
    asm("cvt.rna.tf32.f32 %0, %1;" : "=r"(r) : "f"(f));
    return r;
}
__device__ __forceinline__ void mma_tf32(float* c, const unsigned* a, const unsigned* b) {
    asm volatile(
        "mma.sync.aligned.m16n8k8.row.col.f32.tf32.tf32.f32 "
        "{%0,%1,%2,%3},{%4,%5,%6,%7},{%8,%9},{%0,%1,%2,%3};"
        : "+f"(c[0]), "+f"(c[1]), "+f"(c[2]), "+f"(c[3])
        : "r"(a[0]), "r"(a[1]), "r"(a[2]), "r"(a[3]), "r"(b[0]), "r"(b[1]));
}
__device__ __forceinline__ unsigned packbf2(float lo, float hi) {
    __nv_bfloat162 t = __floats2bfloat162_rn(lo, hi);
    return *(unsigned*)&t;
}

// ---------------- dtype detection --------------------------------------------
__global__ void k_detect(const int* __restrict__ w32, int nwords) {
    __shared__ int nz;
    if (threadIdx.x == 0) nz = 0;
    __syncthreads();
    int pairs = nwords >> 1;
    int lim = min(pairs, 4096);
    for (int i = threadIdx.x; i < lim; i += blockDim.x)
        if (w32[2 * i + 1] != 0) nz = 1;
    __syncthreads();
    if (threadIdx.x == 0) g_is64 = (nz == 0) ? 1 : 0;
}

// ---------------- CSR construction --------------------------------------------
__global__ void k_zero_deg(int n) {
    int i = blockIdx.x * blockDim.x + threadIdx.x;
    if (i < n) g_deg[i] = 0;
}
__global__ void k_count(const void* __restrict__ ei, int E, int Etot, int n) {
    int e = blockIdx.x * blockDim.x + threadIdx.x;
    if (e >= Etot) return;
    int dst = (e < E) ? (int)load_idx(ei, (long long)E + e) : (e - E);
    if (dst >= 0 && dst < n) atomicAdd(&g_deg[dst], 1);
}
// coalesced two-phase scan: stage 10240 elems through smem per phase
__global__ void __launch_bounds__(1024) k_scan(int n) {
    __shared__ int sbuf[10240];
    __shared__ int wsum[32];
    int t = threadIdx.x, lane = t & 31, w = t >> 5;
    int carry = 0;
    #pragma unroll
    for (int ph = 0; ph < 2; ph++) {
        int base = ph * 10240;
        #pragma unroll
        for (int j = 0; j < 10; j++) {
            int idx = base + j * 1024 + t;
            sbuf[j * 1024 + t] = (idx < n) ? g_deg[idx] : 0;
        }
        __syncthreads();
        int vals[10], sum = 0;
        #pragma unroll
        for (int i = 0; i < 10; i++) { vals[i] = sbuf[t * 10 + i]; sum += vals[i]; }
        int s = sum;
        #pragma unroll
        for (int off = 1; off < 32; off <<= 1) {
            int v = __shfl_up_sync(0xffffffffu, s, off);
            if (lane >= off) s += v;
        }
        if (lane == 31) wsum[w] = s;
        __syncthreads();
        if (w == 0) {
            int x = wsum[lane];
            #pragma unroll
            for (int off = 1; off < 32; off <<= 1) {
                int v = __shfl_up_sync(0xffffffffu, x, off);
                if (lane >= off) x += v;
            }
            wsum[lane] = x;
        }
        __syncthreads();
        int excl = s - sum + (w > 0 ? wsum[w - 1] : 0) + carry;
        int total = wsum[31];
        __syncthreads();
        int run = excl;
        #pragma unroll
        for (int i = 0; i < 10; i++) { sbuf[t * 10 + i] = run; run += vals[i]; }
        __syncthreads();
        #pragma unroll
        for (int j = 0; j < 10; j++) {
            int idx = base + j * 1024 + t;
            if (idx < n) { int v = sbuf[j * 1024 + t]; g_row[idx] = v; g_cur[idx] = v; }
        }
        carry += total;
        __syncthreads();
    }
    if (t == 0) g_row[n] = carry;
}
__global__ void k_fill(const void* __restrict__ ei, int E, int Etot, int n) {
    int e = blockIdx.x * blockDim.x + threadIdx.x;
    if (e >= Etot) return;
    int src, dst;
    if (e < E) {
        src = (int)load_idx(ei, e);
        dst = (int)load_idx(ei, (long long)E + e);
    } else { src = e - E; dst = e - E; }
    if (dst < 0 || dst >= n || src < 0 || src >= n) return;
    int pos = atomicAdd(&g_cur[dst], 1);
    g_col[pos] = src;
    g_eid[pos] = e;
}
// graph boundaries from sorted batch: g_goff[g] = first node with batch >= g
__global__ void k_bounds(const void* __restrict__ batch, int n) {
    int i = blockIdx.x * blockDim.x + threadIdx.x;
    if (i >= n) return;
    int b = (int)load_idx(batch, i);
    int prev = (i == 0) ? -1 : (int)load_idx(batch, i - 1);
    for (int g = prev + 1; g <= b && g <= NGRAPH; g++)
        if (g >= 0) g_goff[g] = i;
    if (i == n - 1)
        for (int g = b + 1; g <= NGRAPH; g++) g_goff[g] = n;
}

// ---------------- layer 1 (rank-1, 4 heads) ----------------------------------
__global__ void k_prep1(const float* __restrict__ W1, const float* __restrict__ as1,
                        const float* __restrict__ ad1) {
    __shared__ float ss[256], sd[256];
    int c = threadIdx.x;
    float w = W1[c];
    ss[c] = w * as1[c];
    sd[c] = w * ad1[c];
    __syncthreads();
    for (int off = 32; off; off >>= 1) {
        if ((c & 63) < off) { ss[c] += ss[c + off]; sd[c] += sd[c + off]; }
        __syncthreads();
    }
    if ((c & 63) == 0) { g_cs[c >> 6] = ss[c]; g_cd[c >> 6] = sd[c]; }
}
__global__ void k_sd1(const float* __restrict__ x, int n) {
    int i = blockIdx.x * blockDim.x + threadIdx.x;
    if (i >= n) return;
    float xv = x[i];
    #pragma unroll
    for (int h = 0; h < 4; h++) {
        g_as[i * 4 + h] = xv * g_cs[h];
        g_ad[i * 4 + h] = xv * g_cd[h];
    }
}
__global__ void k_att1(int n) {
    int w = (blockIdx.x * blockDim.x + threadIdx.x) >> 5;
    int lane = threadIdx.x & 31;
    if (w >= n) return;
    int b = g_row[w], e2 = g_row[w + 1];
    float4 ad = ((const float4*)g_ad)[w];
    float4 mx = make_float4(-1e30f, -1e30f, -1e30f, -1e30f);
    for (int p = b + lane; p < e2; p += 32) {
        float4 av = ((const float4*)g_as)[g_col[p]];
        float4 ev;
        ev.x = lrelu(av.x + ad.x); ev.y = lrelu(av.y + ad.y);
        ev.z = lrelu(av.z + ad.z); ev.w = lrelu(av.w + ad.w);
        ((float4*)g_ebuf)[p] = ev;
        mx.x = fmaxf(mx.x, ev.x); mx.y = fmaxf(mx.y, ev.y);
        mx.z = fmaxf(mx.z, ev.z); mx.w = fmaxf(mx.w, ev.w);
    }
    for (int o = 16; o; o >>= 1) {
        mx.x = fmaxf(mx.x, __shfl_xor_sync(0xffffffffu, mx.x, o));
        mx.y = fmaxf(mx.y, __shfl_xor_sync(0xffffffffu, mx.y, o));
        mx.z = fmaxf(mx.z, __shfl_xor_sync(0xffffffffu, mx.z, o));
        mx.w = fmaxf(mx.w, __shfl_xor_sync(0xffffffffu, mx.w, o));
    }
    float4 sm = make_float4(0, 0, 0, 0);
    for (int p = b + lane; p < e2; p += 32) {
        float4 ev = ((float4*)g_ebuf)[p];
        ev.x = expf(ev.x - mx.x); ev.y = expf(ev.y - mx.y);
        ev.z = expf(ev.z - mx.z); ev.w = expf(ev.w - mx.w);
        ((float4*)g_ebuf)[p] = ev;
        sm.x += ev.x; sm.y += ev.y; sm.z += ev.z; sm.w += ev.w;
    }
    for (int o = 16; o; o >>= 1) {
        sm.x += __shfl_xor_sync(0xffffffffu, sm.x, o);
        sm.y += __shfl_xor_sync(0xffffffffu, sm.y, o);
        sm.z += __shfl_xor_sync(0xffffffffu, sm.z, o);
        sm.w += __shfl_xor_sync(0xffffffffu, sm.w, o);
    }
    float4 inv;
    inv.x = 1.f / (sm.x + 1e-16f); inv.y = 1.f / (sm.y + 1e-16f);
    inv.z = 1.f / (sm.z + 1e-16f); inv.w = 1.f / (sm.w + 1e-16f);
    for (int p = b + lane; p < e2; p += 32) {
        float4 ev = ((float4*)g_ebuf)[p];
        ev.x *= inv.x; ev.y *= inv.y; ev.z *= inv.z; ev.w *= inv.w;
        ((float4*)g_ebuf)[p] = ev;
    }
}
__global__ void __launch_bounds__(256) k_agg1(const float* __restrict__ x,
                                              const float* __restrict__ W1,
                                              const float* __restrict__ b1, int n) {
    int d = blockIdx.x;
    if (d >= n) return;
    int tid = threadIdx.x;
    __shared__ float s4[4];
    if (tid < 32) {
        int b = g_row[d], e = g_row[d + 1];
        float4 acc = make_float4(0, 0, 0, 0);
        for (int p = b + tid; p < e; p += 32) {
            float4 al = ((const float4*)g_ebuf)[p];
            float xv = x[g_col[p]];
            acc.x += al.x * xv; acc.y += al.y * xv;
            acc.z += al.z * xv; acc.w += al.w * xv;
        }
        for (int o = 16; o; o >>= 1) {
            acc.x += __shfl_xor_sync(0xffffffffu, acc.x, o);
            acc.y += __shfl_xor_sync(0xffffffffu, acc.y, o);
            acc.z += __shfl_xor_sync(0xffffffffu, acc.z, o);
            acc.w += __shfl_xor_sync(0xffffffffu, acc.w, o);
        }
        if (tid == 0) { s4[0] = acc.x; s4[1] = acc.y; s4[2] = acc.z; s4[3] = acc.w; }
    }
    __syncthreads();
    g_X[d * 256 + tid] = geluf(s4[tid >> 6] * W1[tid] + b1[tid]);
    if (tid == 0) { g_as[d] = 0.f; g_ad[d] = 0.f; }
}

// ---------------- tf32 TC GEMM + fused a_s/a_d epilogue, bf16 H out ----------
__global__ void __launch_bounds__(256) k_gemm(const float* __restrict__ B,
                                              const float* __restrict__ att_s,
                                              const float* __restrict__ att_d, int M) {
    __shared__ unsigned As[32][136];
    __shared__ unsigned Bs[32][72];
    int tid = threadIdx.x;
    int lane = tid & 31;
    int wid = tid >> 5;
    int wm = (wid & 3) * 32;
    int wn = (wid >> 2) * 32;
    int m0 = blockIdx.x * 128;
    int n0 = blockIdx.y * 64;

    float acc[2][4][4];
    #pragma unroll
    for (int mi = 0; mi < 2; mi++)
        #pragma unroll
        for (int ni = 0; ni < 4; ni++)
            #pragma unroll
            for (int q = 0; q < 4; q++) acc[mi][ni][q] = 0.f;

    int am = tid & 31;
    int ak = 4 * (tid >> 5);
    int bn = 4 * (tid & 15);
    int bk = tid >> 4;

    float4 va[4], vb[2];
    #pragma unroll
    for (int p = 0; p < 4; p++) {
        int gm = m0 + p * 32 + am;
        va[p] = make_float4(0, 0, 0, 0);
        if (gm < M) va[p] = *(const float4*)&g_X[gm * 256 + ak];
    }
    #pragma unroll
    for (int p = 0; p < 2; p++)
        vb[p] = *(const float4*)&B[(bk + p * 16) * 256 + n0 + bn];

    for (int k0 = 0; k0 < 256; k0 += 32) {
        #pragma unroll
        for (int p = 0; p < 4; p++) {
            int sm_ = p * 32 + am;
            As[ak + 0][sm_] = f2tf32(va[p].x);
            As[ak + 1][sm_] = f2tf32(va[p].y);
            As[ak + 2][sm_] = f2tf32(va[p].z);
            As[ak + 3][sm_] = f2tf32(va[p].w);
        }
        #pragma unroll
        for (int p = 0; p < 2; p++) {
            int kk = bk + p * 16;
            Bs[kk][bn + 0] = f2tf32(vb[p].x);
            Bs[kk][bn + 1] = f2tf32(vb[p].y);
            Bs[kk][bn + 2] = f2tf32(vb[p].z);
            Bs[kk][bn + 3] = f2tf32(vb[p].w);
        }
        __syncthreads();
        if (k0 + 32 < 256) {
            int kn = k0 + 32;
            #pragma unroll
            for (int p = 0; p < 4; p++) {
                int gm = m0 + p * 32 + am;
                va[p] = make_float4(0, 0, 0, 0);
                if (gm < M) va[p] = *(const float4*)&g_X[gm * 256 + kn + ak];
            }
            #pragma unroll
            for (int p = 0; p < 2; p++)
                vb[p] = *(const float4*)&B[(kn + bk + p * 16) * 256 + n0 + bn];
        }
        #pragma unroll
        for (int ks = 0; ks < 4; ks++) {
            int kb = ks * 8;
            int c4 = lane & 3, r8 = lane >> 2;
            unsigned a[2][4], bf[4][2];
            #pragma unroll
            for (int mi = 0; mi < 2; mi++) {
                int mr = wm + mi * 16 + r8;
                a[mi][0] = As[kb + c4][mr];
                a[mi][1] = As[kb + c4][mr + 8];
                a[mi][2] = As[kb + c4 + 4][mr];
                a[mi][3] = As[kb + c4 + 4][mr + 8];
            }
            #pragma unroll
            for (int ni = 0; ni < 4; ni++) {
                int nc = wn + ni * 8 + r8;
                bf[ni][0] = Bs[kb + c4][nc];
                bf[ni][1] = Bs[kb + c4 + 4][nc];
            }
            #pragma unroll
            for (int mi = 0; mi < 2; mi++)
                #pragma unroll
                for (int ni = 0; ni < 4; ni++)
                    mma_tf32(acc[mi][ni], a[mi], bf[ni]);
        }
        __syncthreads();
    }
    int r8 = lane >> 2, c4 = lane & 3;
    float pas[4] = {0, 0, 0, 0}, pad_[4] = {0, 0, 0, 0};
    #pragma unroll
    for (int mi = 0; mi < 2; mi++) {
        int m = m0 + wm + mi * 16 + r8;
        #pragma unroll
        for (int ni = 0; ni < 4; ni++) {
            int nn = n0 + wn + ni * 8 + 2 * c4;
            float s0 = __ldg(&att_s[nn]), s1 = __ldg(&att_s[nn + 1]);
            float d0 = __ldg(&att_d[nn]), d1 = __ldg(&att_d[nn + 1]);
            pas[2 * mi]     += acc[mi][ni][0] * s0 + acc[mi][ni][1] * s1;
            pas[2 * mi + 1] += acc[mi][ni][2] * s0 + acc[mi][ni][3] * s1;
            pad_[2 * mi]     += acc[mi][ni][0] * d0 + acc[mi][ni][1] * d1;
            pad_[2 * mi + 1] += acc[mi][ni][2] * d0 + acc[mi][ni][3] * d1;
            if (m < M)
                g_Hb[m * 128 + (nn >> 1)] = packbf2(acc[mi][ni][0], acc[mi][ni][1]);
            if (m + 8 < M)
                g_Hb[(m + 8) * 128 + (nn >> 1)] = packbf2(acc[mi][ni][2], acc[mi][ni][3]);
        }
    }
    #pragma unroll
    for (int off = 1; off < 4; off <<= 1) {
        #pragma unroll
        for (int r = 0; r < 4; r++) {
            pas[r]  += __shfl_xor_sync(0xffffffffu, pas[r], off);
            pad_[r] += __shfl_xor_sync(0xffffffffu, pad_[r], off);
        }
    }
    if (c4 == 0) {
        #pragma unroll
        for (int r = 0; r < 4; r++) {
            int row = wm + r8 + (r & 1) * 8 + (r >> 1) * 16;
            int m = m0 + row;
            if (m < M) {
                atomicAdd(&g_as[m], pas[r]);
                atomicAdd(&g_ad[m], pad_[r]);
            }
        }
    }
}

// ---------------- edge softmax (heads=1), warp per dst -----------------------
__global__ void k_att2(int n, float* alpha_out) {
    int d = (blockIdx.x * blockDim.x + threadIdx.x) >> 5;
    int lane = threadIdx.x & 31;
    if (d >= n) return;
    int b = g_row[d], e = g_row[d + 1];
    float ad = g_ad[d];
    float mx = -1e30f;
    for (int p = b + lane; p < e; p += 32) {
        float ev = lrelu(g_as[g_col[p]] + ad);
        g_ebuf[p] = ev;
        mx = fmaxf(mx, ev);
    }
    for (int o = 16; o; o >>= 1) mx = fmaxf(mx, __shfl_xor_sync(0xffffffffu, mx, o));
    float sm = 0.f;
    for (int p = b + lane; p < e; p += 32) {
        float ex = expf(g_ebuf[p] - mx);
        g_ebuf[p] = ex;
        sm += ex;
    }
    for (int o = 16; o; o >>= 1) sm += __shfl_xor_sync(0xffffffffu, sm, o);
    float inv = 1.f / (sm + 1e-16f);
    for (int p = b + lane; p < e; p += 32) {
        float al = g_ebuf[p] * inv;
        g_ebuf[p] = al;
        if (alpha_out) alpha_out[g_eid[p]] = al;
    }
}

// ---------------- aggregation: warp per dst, bf16 gather (uint4 = 8 ch) ------
__global__ void __launch_bounds__(256) k_agg2(const float* __restrict__ bias, int n) {
    int wid = threadIdx.x >> 5, lane = threadIdx.x & 31;
    int d = blockIdx.x * 8 + wid;
    if (d >= n) return;
    int b = g_row[d], e = g_row[d + 1];
    float acc[8];
    #pragma unroll
    for (int j = 0; j < 8; j++) acc[j] = 0.f;
    for (int base = b; base < e; base += 32) {
        int p = base + lane;
        float aa = 0.f; int cc = 0;
        if (p < e) { aa = g_ebuf[p]; cc = g_col[p]; }
        int lim = min(32, e - base);
        #pragma unroll 4
        for (int i = 0; i < lim; i++) {
            int   c = __shfl_sync(0xffffffffu, cc, i);
            float a = __shfl_sync(0xffffffffu, aa, i);
            uint4 v = ((const uint4*)&g_Hb[c * 128])[lane];
            float2 f0 = __bfloat1622float2(*(__nv_bfloat162*)&v.x);
            float2 f1 = __bfloat1622float2(*(__nv_bfloat162*)&v.y);
            float2 f2 = __bfloat1622float2(*(__nv_bfloat162*)&v.z);
            float2 f3 = __bfloat1622float2(*(__nv_bfloat162*)&v.w);
            acc[0] += a * f0.x; acc[1] += a * f0.y;
            acc[2] += a * f1.x; acc[3] += a * f1.y;
            acc[4] += a * f2.x; acc[5] += a * f2.y;
            acc[6] += a * f3.x; acc[7] += a * f3.y;
        }
    }
    float4 o0, o1;
    const float4* bv = (const float4*)&bias[lane * 8];
    float4 b0 = bv[0], b1 = bv[1];
    o0.x = geluf(acc[0] + b0.x); o0.y = geluf(acc[1] + b0.y);
    o0.z = geluf(acc[2] + b0.z); o0.w = geluf(acc[3] + b0.w);
    o1.x = geluf(acc[4] + b1.x); o1.y = geluf(acc[5] + b1.y);
    o1.z = geluf(acc[6] + b1.z); o1.w = geluf(acc[7] + b1.w);
    float4* xp = (float4*)&g_X[d * 256 + lane * 8];
    xp[0] = o0; xp[1] = o1;
    if (lane == 0) { g_as[d] = 0.f; g_ad[d] = 0.f; }
}

// ---------------- pooling (atomic-free, per-graph blocks) + MLP --------------
__global__ void __launch_bounds__(256) k_pool2() {
    __shared__ float sbuf[4][256];
    int g = blockIdx.x;
    int s = threadIdx.x >> 6, c4 = threadIdx.x & 63;
    int b = g_goff[g], e = g_goff[g + 1];
    float4 acc = make_float4(0, 0, 0, 0);
    for (int i = b + s; i < e; i += 4) {
        float4 v = *(const float4*)&g_X[i * 256 + c4 * 4];
        acc.x += v.x; acc.y += v.y; acc.z += v.z; acc.w += v.w;
    }
    *(float4*)&sbuf[s][c4 * 4] = acc;
    __syncthreads();
    if (s == 0) {
        #pragma unroll
        for (int k = 0; k < 4; k++) {
            int c = c4 * 4 + k;
            g_gsum[g * 256 + c] = sbuf[0][c] + sbuf[1][c] + sbuf[2][c] + sbuf[3][c];
        }
    }
}
__global__ void __launch_bounds__(512) k_mlp(const float* __restrict__ Wl1, const float* __restrict__ bl1,
                                             const float* __restrict__ Wl2, const float* __restrict__ bl2,
                                             const float* __restrict__ Wl3, const float* __restrict__ bl3,
                                             float* __restrict__ out) {
    __shared__ float G[16 * 256];
    __shared__ float G1[16 * 128];
    __shared__ float G2[16 * 64];
    int t = threadIdx.x;
    for (int i = t; i < 4096; i += 512) {
        int g = i >> 8;
        int cnt = g_goff[g + 1] - g_goff[g];
        G[i] = g_gsum[i] / (float)(cnt > 0 ? cnt : 1);
    }
    __syncthreads();
    for (int i = t; i < 2048; i += 512) {
        int gi = i >> 7, j = i & 127;
        float a = bl1[j];
        for (int k = 0; k < 256; k++) a += G[gi * 256 + k] * Wl1[k * 128 + j];
        G1[i] = geluf(a);
    }
    __syncthreads();
    for (int i = t; i < 1024; i += 512) {
        int gi = i >> 6, j = i & 63;
        float a = bl2[j];
        for (int k = 0; k < 128; k++) a += G1[gi * 128 + k] * Wl2[k * 64 + j];
        G2[i] = geluf(a);
    }
    __syncthreads();
    if (t < 16) {
        float a = bl3[0];
        for (int k = 0; k < 64; k++) a += G2[t * 64 + k] * Wl3[k];
        out[t] = 1.f / (1.f + expf(-a));
    }
}

// ---------------- attn_edge_index output --------------------------------------
__global__ void k_attn_idx(const void* __restrict__ ei, int E, int Etot,
                           float* __restrict__ dst) {
    int i = blockIdx.x * blockDim.x + threadIdx.x;
    if (i >= 2 * Etot) return;
    int which = i / Etot;
    int e = i - which * Etot;
    long long v = (e < E) ? load_idx(ei, (long long)which * E + e)
                          : (long long)(e - E);
    dst[i] = (float)v;
}

// ---------------- host launcher ------------------------------------------------
extern "C" void kernel_launch(void* const* d_in, const int* in_sizes, int n_in,
                              void* d_out, int out_size) {
    const float* x     = (const float*)d_in[0];
    const void*  ei    = d_in[1];
    const void*  batch = d_in[2];
    const float* W1  = (const float*)d_in[3];
    const float* as1 = (const float*)d_in[4];
    const float* ad1 = (const float*)d_in[5];
    const float* b1  = (const float*)d_in[6];
    const float* W2  = (const float*)d_in[7];
    const float* as2 = (const float*)d_in[8];
    const float* ad2 = (const float*)d_in[9];
    const float* b2  = (const float*)d_in[10];
    const float* Wl1 = (const float*)d_in[11];
    const float* bl1 = (const float*)d_in[12];
    const float* Wl2 = (const float*)d_in[13];
    const float* bl2 = (const float*)d_in[14];
    const float* Wl3 = (const float*)d_in[15];
    const float* bl3 = (const float*)d_in[16];

    int Nn = in_sizes[0];
    int E = in_sizes[1] / 2;
    int Etot = E + Nn;
    float* out = (float*)d_out;
    bool full = (out_size >= 16 + 3 * Etot);
    float* alpha_out = full ? (out + 16 + 2 * Etot) : nullptr;

    // ---- dtype detection (int32 vs int64 edge/batch arrays) ----
    k_detect<<<1, 256>>>((const int*)ei, 2 * E);

    // ---- CSR (counting sort by dst) + graph boundaries ----
    k_zero_deg<<<(Nn + 255) / 256, 256>>>(Nn);
    k_count<<<(Etot + 255) / 256, 256>>>(ei, E, Etot, Nn);
    k_scan<<<1, 1024>>>(Nn);
    k_fill<<<(Etot + 255) / 256, 256>>>(ei, E, Etot, Nn);
    k_bounds<<<(Nn + 255) / 256, 256>>>(batch, Nn);

    // ---- layer 1 (GATConv(1, 64, heads=4), rank-1 collapse) ----
    k_prep1<<<1, 256>>>(W1, as1, ad1);
    k_sd1<<<(Nn + 255) / 256, 256>>>(x, Nn);
    k_att1<<<(Nn + 7) / 8, 256>>>(Nn);
    k_agg1<<<Nn, 256>>>(x, W1, b1, Nn);

    // ---- layers 2-4 (GATConv(256, 256, heads=1)) ----
    for (int l = 0; l < 3; l++) {
        k_gemm<<<dim3((Nn + 127) / 128, 4), 256>>>(W2 + l * 65536,
                                                   as2 + l * 256, ad2 + l * 256, Nn);
        k_att2<<<(Nn + 7) / 8, 256>>>(Nn, (l == 2) ? alpha_out : nullptr);
        k_agg2<<<(Nn + 7) / 8, 256>>>(b2 + l * 256, Nn);
    }

    // ---- mean pool + MLP head ----
    k_pool2<<<NGRAPH, 256>>>();
    k_mlp<<<1, 512>>>(Wl1, bl1, Wl2, bl2, Wl3, bl3, out);

    // ---- attn_edge_index output ----
    if (full) k_attn_idx<<<(2 * Etot + 255) / 256, 256>>>(ei, E, Etot, out + 16);
}

// round 6
// speedup vs baseline: 1.4875x; 1.0386x over previous
#include <cuda_runtime.h>
#include <cuda_bf16.h>
#include <math.h>

#define NMAX   20000
#define ETOT_MAX 340000
#define DD     256
#define NGRAPH 16

// ---------------- scratch (static device globals; no allocation) -------------
__device__ float    g_X[NMAX * DD];      // current features (layer input/output)
__device__ unsigned g_Hb[NMAX * 128];    // post-GEMM features, bf16x2 packed
__device__ float    g_as[NMAX * 4];      // L1: 4-head src logits; L2-4: 4 src partials
__device__ float    g_ad[NMAX * 4];      // L1: 4-head dst logits; L2-4: 4 dst partials
__device__ int      g_deg[NMAX];
__device__ int      g_row[NMAX + 1];
__device__ int      g_cur[NMAX];
__device__ int      g_col[ETOT_MAX];     // src node per CSR slot
__device__ int      g_eid[ETOT_MAX];     // original edge id per CSR slot
__device__ float    g_cs[4], g_cd[4];    // layer-1 collapsed attention weights
__device__ float    g_gsum[NGRAPH * DD];
__device__ int      g_goff[NGRAPH + 1];  // graph node-range boundaries (sorted batch)
__device__ int      g_is64;              // 1 if edge_index/batch are int64

// ---------------- helpers ----------------------------------------------------
__device__ __forceinline__ float geluf(float x) {
    float t = tanhf(0.7978845608028654f * (x + 0.044715f * x * x * x));
    return 0.5f * x * (1.0f + t);
}
__device__ __forceinline__ float lrelu(float x) { return x > 0.f ? x : 0.2f * x; }

__device__ __forceinline__ long long load_idx(const void* p, long long i) {
    if (g_is64) return ((const long long*)p)[i];
    return (long long)((const int*)p)[i];
}

__device__ __forceinline__ unsigned f2tf32(float f) {
    unsigned r;
    asm("cvt.rna.tf32.f32 %0, %1;" : "=r"(r) : "f"(f));
    return r;
}
__device__ __forceinline__ void mma_tf32(float* c, const unsigned* a, const unsigned* b) {
    asm volatile(
        "mma.sync.aligned.m16n8k8.row.col.f32.tf32.tf32.f32 "
        "{%0,%1,%2,%3},{%4,%5,%6,%7},{%8,%9},{%0,%1,%2,%3};"
        : "+f"(c[0]), "+f"(c[1]), "+f"(c[2]), "+f"(c[3])
        : "r"(a[0]), "r"(a[1]), "r"(a[2]), "r"(a[3]), "r"(b[0]), "r"(b[1]));
}
__device__ __forceinline__ unsigned packbf2(float lo, float hi) {
    __nv_bfloat162 t = __floats2bfloat162_rn(lo, hi);
    return *(unsigned*)&t;
}

// ---------------- dtype detection --------------------------------------------
__global__ void k_detect(const int* __restrict__ w32, int nwords) {
    __shared__ int nz;
    if (threadIdx.x == 0) nz = 0;
    __syncthreads();
    int pairs = nwords >> 1;
    int lim = min(pairs, 4096);
    for (int i = threadIdx.x; i < lim; i += blockDim.x)
        if (w32[2 * i + 1] != 0) nz = 1;
    __syncthreads();
    if (threadIdx.x == 0) g_is64 = (nz == 0) ? 1 : 0;
}

// ---------------- CSR construction --------------------------------------------
__global__ void k_zero_deg(int n) {
    int i = blockIdx.x * blockDim.x + threadIdx.x;
    if (i < n) g_deg[i] = 0;
}
__global__ void k_count(const void* __restrict__ ei, int E, int Etot, int n) {
    int e = blockIdx.x * blockDim.x + threadIdx.x;
    if (e >= Etot) return;
    int dst = (e < E) ? (int)load_idx(ei, (long long)E + e) : (e - E);
    if (dst >= 0 && dst < n) atomicAdd(&g_deg[dst], 1);
}
// coalesced two-phase scan: stage 10240 elems through smem per phase
__global__ void __launch_bounds__(1024) k_scan(int n) {
    __shared__ int sbuf[10240];
    __shared__ int wsum[32];
    int t = threadIdx.x, lane = t & 31, w = t >> 5;
    int carry = 0;
    #pragma unroll
    for (int ph = 0; ph < 2; ph++) {
        int base = ph * 10240;
        #pragma unroll
        for (int j = 0; j < 10; j++) {
            int idx = base + j * 1024 + t;
            sbuf[j * 1024 + t] = (idx < n) ? g_deg[idx] : 0;
        }
        __syncthreads();
        int vals[10], sum = 0;
        #pragma unroll
        for (int i = 0; i < 10; i++) { vals[i] = sbuf[t * 10 + i]; sum += vals[i]; }
        int s = sum;
        #pragma unroll
        for (int off = 1; off < 32; off <<= 1) {
            int v = __shfl_up_sync(0xffffffffu, s, off);
            if (lane >= off) s += v;
        }
        if (lane == 31) wsum[w] = s;
        __syncthreads();
        if (w == 0) {
            int x = wsum[lane];
            #pragma unroll
            for (int off = 1; off < 32; off <<= 1) {
                int v = __shfl_up_sync(0xffffffffu, x, off);
                if (lane >= off) x += v;
            }
            wsum[lane] = x;
        }
        __syncthreads();
        int excl = s - sum + (w > 0 ? wsum[w - 1] : 0) + carry;
        int total = wsum[31];
        __syncthreads();
        int run = excl;
        #pragma unroll
        for (int i = 0; i < 10; i++) { sbuf[t * 10 + i] = run; run += vals[i]; }
        __syncthreads();
        #pragma unroll
        for (int j = 0; j < 10; j++) {
            int idx = base + j * 1024 + t;
            if (idx < n) { int v = sbuf[j * 1024 + t]; g_row[idx] = v; g_cur[idx] = v; }
        }
        carry += total;
        __syncthreads();
    }
    if (t == 0) g_row[n] = carry;
}
__global__ void k_fill(const void* __restrict__ ei, int E, int Etot, int n) {
    int e = blockIdx.x * blockDim.x + threadIdx.x;
    if (e >= Etot) return;
    int src, dst;
    if (e < E) {
        src = (int)load_idx(ei, e);
        dst = (int)load_idx(ei, (long long)E + e);
    } else { src = e - E; dst = e - E; }
    if (dst < 0 || dst >= n || src < 0 || src >= n) return;
    int pos = atomicAdd(&g_cur[dst], 1);
    g_col[pos] = src;
    g_eid[pos] = e;
}
// graph boundaries from sorted batch
__global__ void k_bounds(const void* __restrict__ batch, int n) {
    int i = blockIdx.x * blockDim.x + threadIdx.x;
    if (i >= n) return;
    int b = (int)load_idx(batch, i);
    int prev = (i == 0) ? -1 : (int)load_idx(batch, i - 1);
    for (int g = prev + 1; g <= b && g <= NGRAPH; g++)
        if (g >= 0) g_goff[g] = i;
    if (i == n - 1)
        for (int g = b + 1; g <= NGRAPH; g++) g_goff[g] = n;
}

// ---------------- layer 1 (rank-1, 4 heads) ----------------------------------
__global__ void k_prep1(const float* __restrict__ W1, const float* __restrict__ as1,
                        const float* __restrict__ ad1) {
    __shared__ float ss[256], sd[256];
    int c = threadIdx.x;
    float w = W1[c];
    ss[c] = w * as1[c];
    sd[c] = w * ad1[c];
    __syncthreads();
    for (int off = 32; off; off >>= 1) {
        if ((c & 63) < off) { ss[c] += ss[c + off]; sd[c] += sd[c + off]; }
        __syncthreads();
    }
    if ((c & 63) == 0) { g_cs[c >> 6] = ss[c]; g_cd[c >> 6] = sd[c]; }
}
__global__ void k_sd1(const float* __restrict__ x, int n) {
    int i = blockIdx.x * blockDim.x + threadIdx.x;
    if (i >= n) return;
    float xv = x[i];
    #pragma unroll
    for (int h = 0; h < 4; h++) {
        g_as[i * 4 + h] = xv * g_cs[h];
        g_ad[i * 4 + h] = xv * g_cd[h];
    }
}
// fused layer-1: softmax (4 heads) + aggregate + W1 expand + gelu, warp/dst
__global__ void __launch_bounds__(256) k_fused1(const float* __restrict__ x,
                                                const float* __restrict__ W1,
                                                const float* __restrict__ b1, int n) {
    int wid = threadIdx.x >> 5, lane = threadIdx.x & 31;
    int d = blockIdx.x * 8 + wid;
    if (d >= n) return;
    int b = g_row[d], e = g_row[d + 1];
    float4 ad = ((const float4*)g_ad)[d];
    const int NC = 4;                  // cache 128 edges/dst in regs
    float4 ev[NC]; float xv[NC];
    float4 mx = make_float4(-1e30f, -1e30f, -1e30f, -1e30f);
    int i = 0;
    for (int p = b + lane; p < e; p += 32, i++) {
        int c = g_col[p];
        float4 av = ((const float4*)g_as)[c];
        float4 v;
        v.x = lrelu(av.x + ad.x); v.y = lrelu(av.y + ad.y);
        v.z = lrelu(av.z + ad.z); v.w = lrelu(av.w + ad.w);
        float xx = x[c];
        if (i < NC) { ev[i] = v; xv[i] = xx; }
        mx.x = fmaxf(mx.x, v.x); mx.y = fmaxf(mx.y, v.y);
        mx.z = fmaxf(mx.z, v.z); mx.w = fmaxf(mx.w, v.w);
    }
    #pragma unroll
    for (int o = 16; o; o >>= 1) {
        mx.x = fmaxf(mx.x, __shfl_xor_sync(0xffffffffu, mx.x, o));
        mx.y = fmaxf(mx.y, __shfl_xor_sync(0xffffffffu, mx.y, o));
        mx.z = fmaxf(mx.z, __shfl_xor_sync(0xffffffffu, mx.z, o));
        mx.w = fmaxf(mx.w, __shfl_xor_sync(0xffffffffu, mx.w, o));
    }
    float4 sm = make_float4(0, 0, 0, 0);
    i = 0;
    for (int p = b + lane; p < e; p += 32, i++) {
        float4 v;
        if (i < NC) v = ev[i];
        else {
            int c = g_col[p];
            float4 av = ((const float4*)g_as)[c];
            v.x = lrelu(av.x + ad.x); v.y = lrelu(av.y + ad.y);
            v.z = lrelu(av.z + ad.z); v.w = lrelu(av.w + ad.w);
        }
        v.x = expf(v.x - mx.x); v.y = expf(v.y - mx.y);
        v.z = expf(v.z - mx.z); v.w = expf(v.w - mx.w);
        if (i < NC) ev[i] = v;
        sm.x += v.x; sm.y += v.y; sm.z += v.z; sm.w += v.w;
    }
    #pragma unroll
    for (int o = 16; o; o >>= 1) {
        sm.x += __shfl_xor_sync(0xffffffffu, sm.x, o);
        sm.y += __shfl_xor_sync(0xffffffffu, sm.y, o);
        sm.z += __shfl_xor_sync(0xffffffffu, sm.z, o);
        sm.w += __shfl_xor_sync(0xffffffffu, sm.w, o);
    }
    float4 inv;
    inv.x = 1.f / (sm.x + 1e-16f); inv.y = 1.f / (sm.y + 1e-16f);
    inv.z = 1.f / (sm.z + 1e-16f); inv.w = 1.f / (sm.w + 1e-16f);
    float4 acc = make_float4(0, 0, 0, 0);
    i = 0;
    for (int p = b + lane; p < e; p += 32, i++) {
        float4 al; float xx;
        if (i < NC) { al = ev[i]; xx = xv[i]; }
        else {
            int c = g_col[p];
            float4 av = ((const float4*)g_as)[c];
            al.x = expf(lrelu(av.x + ad.x) - mx.x);
            al.y = expf(lrelu(av.y + ad.y) - mx.y);
            al.z = expf(lrelu(av.z + ad.z) - mx.z);
            al.w = expf(lrelu(av.w + ad.w) - mx.w);
            xx = x[c];
        }
        acc.x += al.x * inv.x * xx; acc.y += al.y * inv.y * xx;
        acc.z += al.z * inv.z * xx; acc.w += al.w * inv.w * xx;
    }
    #pragma unroll
    for (int o = 16; o; o >>= 1) {
        acc.x += __shfl_xor_sync(0xffffffffu, acc.x, o);
        acc.y += __shfl_xor_sync(0xffffffffu, acc.y, o);
        acc.z += __shfl_xor_sync(0xffffffffu, acc.z, o);
        acc.w += __shfl_xor_sync(0xffffffffu, acc.w, o);
    }
    int head = lane >> 3;              // 8 channels per lane, 64 per head
    float hv = (head == 0) ? acc.x : (head == 1) ? acc.y : (head == 2) ? acc.z : acc.w;
    int c0 = lane * 8;
    const float4* wp = (const float4*)&W1[c0];
    const float4* bp = (const float4*)&b1[c0];
    float4 w0 = wp[0], w1 = wp[1], bb0 = bp[0], bb1 = bp[1];
    float4 o0, o1;
    o0.x = geluf(hv * w0.x + bb0.x); o0.y = geluf(hv * w0.y + bb0.y);
    o0.z = geluf(hv * w0.z + bb0.z); o0.w = geluf(hv * w0.w + bb0.w);
    o1.x = geluf(hv * w1.x + bb1.x); o1.y = geluf(hv * w1.y + bb1.y);
    o1.z = geluf(hv * w1.z + bb1.z); o1.w = geluf(hv * w1.w + bb1.w);
    float4* xp = (float4*)&g_X[d * 256 + c0];
    xp[0] = o0; xp[1] = o1;
}

// ---------------- tf32 TC GEMM + deterministic partial logit epilogue --------
// g_H(bf16) = g_X @ W; writes g_as[m*4+j], g_ad[m*4+j] partials (j = y*2+wng).
__global__ void __launch_bounds__(256) k_gemm(const float* __restrict__ B,
                                              const float* __restrict__ att_s,
                                              const float* __restrict__ att_d, int M) {
    __shared__ unsigned As[32][136];
    __shared__ unsigned Bs[32][72];
    __shared__ float s_pas[128], s_pad[128];
    int tid = threadIdx.x;
    int lane = tid & 31;
    int wid = tid >> 5;
    int wm = (wid & 3) * 32;
    int wng = wid >> 2;
    int wn = wng * 32;
    int m0 = blockIdx.x * 128;
    int n0 = blockIdx.y * 64;

    float acc[2][4][4];
    #pragma unroll
    for (int mi = 0; mi < 2; mi++)
        #pragma unroll
        for (int ni = 0; ni < 4; ni++)
            #pragma unroll
            for (int q = 0; q < 4; q++) acc[mi][ni][q] = 0.f;

    int am = tid & 31;
    int ak = 4 * (tid >> 5);
    int bn = 4 * (tid & 15);
    int bk = tid >> 4;

    float4 va[4], vb[2];
    #pragma unroll
    for (int p = 0; p < 4; p++) {
        int gm = m0 + p * 32 + am;
        va[p] = make_float4(0, 0, 0, 0);
        if (gm < M) va[p] = *(const float4*)&g_X[gm * 256 + ak];
    }
    #pragma unroll
    for (int p = 0; p < 2; p++)
        vb[p] = *(const float4*)&B[(bk + p * 16) * 256 + n0 + bn];

    for (int k0 = 0; k0 < 256; k0 += 32) {
        #pragma unroll
        for (int p = 0; p < 4; p++) {
            int sm_ = p * 32 + am;
            As[ak + 0][sm_] = f2tf32(va[p].x);
            As[ak + 1][sm_] = f2tf32(va[p].y);
            As[ak + 2][sm_] = f2tf32(va[p].z);
            As[ak + 3][sm_] = f2tf32(va[p].w);
        }
        #pragma unroll
        for (int p = 0; p < 2; p++) {
            int kk = bk + p * 16;
            Bs[kk][bn + 0] = f2tf32(vb[p].x);
            Bs[kk][bn + 1] = f2tf32(vb[p].y);
            Bs[kk][bn + 2] = f2tf32(vb[p].z);
            Bs[kk][bn + 3] = f2tf32(vb[p].w);
        }
        __syncthreads();
        if (k0 + 32 < 256) {
            int kn = k0 + 32;
            #pragma unroll
            for (int p = 0; p < 4; p++) {
                int gm = m0 + p * 32 + am;
                va[p] = make_float4(0, 0, 0, 0);
                if (gm < M) va[p] = *(const float4*)&g_X[gm * 256 + kn + ak];
            }
            #pragma unroll
            for (int p = 0; p < 2; p++)
                vb[p] = *(const float4*)&B[(kn + bk + p * 16) * 256 + n0 + bn];
        }
        #pragma unroll
        for (int ks = 0; ks < 4; ks++) {
            int kb = ks * 8;
            int c4 = lane & 3, r8 = lane >> 2;
            unsigned a[2][4], bf[4][2];
            #pragma unroll
            for (int mi = 0; mi < 2; mi++) {
                int mr = wm + mi * 16 + r8;
                a[mi][0] = As[kb + c4][mr];
                a[mi][1] = As[kb + c4][mr + 8];
                a[mi][2] = As[kb + c4 + 4][mr];
                a[mi][3] = As[kb + c4 + 4][mr + 8];
            }
            #pragma unroll
            for (int ni = 0; ni < 4; ni++) {
                int nc = wn + ni * 8 + r8;
                bf[ni][0] = Bs[kb + c4][nc];
                bf[ni][1] = Bs[kb + c4 + 4][nc];
            }
            #pragma unroll
            for (int mi = 0; mi < 2; mi++)
                #pragma unroll
                for (int ni = 0; ni < 4; ni++)
                    mma_tf32(acc[mi][ni], a[mi], bf[ni]);
        }
        __syncthreads();
    }
    int r8 = lane >> 2, c4 = lane & 3;
    float pas[4] = {0, 0, 0, 0}, pad_[4] = {0, 0, 0, 0};
    #pragma unroll
    for (int mi = 0; mi < 2; mi++) {
        int m = m0 + wm + mi * 16 + r8;
        #pragma unroll
        for (int ni = 0; ni < 4; ni++) {
            int nn = n0 + wn + ni * 8 + 2 * c4;
            float s0 = __ldg(&att_s[nn]), s1 = __ldg(&att_s[nn + 1]);
            float d0 = __ldg(&att_d[nn]), d1 = __ldg(&att_d[nn + 1]);
            pas[2 * mi]     += acc[mi][ni][0] * s0 + acc[mi][ni][1] * s1;
            pas[2 * mi + 1] += acc[mi][ni][2] * s0 + acc[mi][ni][3] * s1;
            pad_[2 * mi]     += acc[mi][ni][0] * d0 + acc[mi][ni][1] * d1;
            pad_[2 * mi + 1] += acc[mi][ni][2] * d0 + acc[mi][ni][3] * d1;
            if (m < M)
                g_Hb[m * 128 + (nn >> 1)] = packbf2(acc[mi][ni][0], acc[mi][ni][1]);
            if (m + 8 < M)
                g_Hb[(m + 8) * 128 + (nn >> 1)] = packbf2(acc[mi][ni][2], acc[mi][ni][3]);
        }
    }
    #pragma unroll
    for (int off = 1; off < 4; off <<= 1) {
        #pragma unroll
        for (int r = 0; r < 4; r++) {
            pas[r]  += __shfl_xor_sync(0xffffffffu, pas[r], off);
            pad_[r] += __shfl_xor_sync(0xffffffffu, pad_[r], off);
        }
    }
    // combine the two n-group warps via smem, then one deterministic write
    if (c4 == 0 && wng == 1) {
        #pragma unroll
        for (int r = 0; r < 4; r++) {
            int row = wm + r8 + (r & 1) * 8 + (r >> 1) * 16;
            s_pas[row] = pas[r]; s_pad[row] = pad_[r];
        }
    }
    __syncthreads();
    if (c4 == 0 && wng == 0) {
        #pragma unroll
        for (int r = 0; r < 4; r++) {
            int row = wm + r8 + (r & 1) * 8 + (r >> 1) * 16;
            int m = m0 + row;
            if (m < M) {
                g_as[m * 4 + blockIdx.y] = pas[r] + s_pas[row];
                g_ad[m * 4 + blockIdx.y] = pad_[r] + s_pad[row];
            }
        }
    }
}

// ------- fused edge softmax + aggregation (layers 2-4), warp per dst ---------
__global__ void __launch_bounds__(256) k_fatt(const float* __restrict__ bias, int n,
                                              float* __restrict__ alpha_out) {
    int wid = threadIdx.x >> 5, lane = threadIdx.x & 31;
    int d = blockIdx.x * 8 + wid;
    if (d >= n) return;
    int b = g_row[d], e = g_row[d + 1];
    float4 dv = ((const float4*)g_ad)[d];
    float ad = (dv.x + dv.y) + (dv.z + dv.w);
    const int NC = 8;                  // cache 256 edges/dst in regs
    float ev[NC]; int col[NC];
    float mx = -1e30f;
    int i = 0;
    for (int p = b + lane; p < e; p += 32, i++) {
        int c = g_col[p];
        float4 sv = ((const float4*)g_as)[c];
        float v = lrelu((sv.x + sv.y) + (sv.z + sv.w) + ad);
        if (i < NC) { ev[i] = v; col[i] = c; }
        mx = fmaxf(mx, v);
    }
    #pragma unroll
    for (int o = 16; o; o >>= 1) mx = fmaxf(mx, __shfl_xor_sync(0xffffffffu, mx, o));
    float sm = 0.f;
    i = 0;
    for (int p = b + lane; p < e; p += 32, i++) {
        float v;
        if (i < NC) v = ev[i];
        else {
            float4 sv = ((const float4*)g_as)[g_col[p]];
            v = lrelu((sv.x + sv.y) + (sv.z + sv.w) + ad);
        }
        v = expf(v - mx);
        if (i < NC) ev[i] = v;
        sm += v;
    }
    #pragma unroll
    for (int o = 16; o; o >>= 1) sm += __shfl_xor_sync(0xffffffffu, sm, o);
    float inv = 1.f / (sm + 1e-16f);

    float acc[8];
    #pragma unroll
    for (int j = 0; j < 8; j++) acc[j] = 0.f;
    for (int base = b; base < e; base += 32) {
        int p = base + lane;
        int idx = (base - b) >> 5;
        float aa = 0.f; int cc = 0;
        if (p < e) {
            if (idx < NC) { aa = ev[idx] * inv; cc = col[idx]; }
            else {
                cc = g_col[p];
                float4 sv = ((const float4*)g_as)[cc];
                aa = expf(lrelu((sv.x + sv.y) + (sv.z + sv.w) + ad) - mx) * inv;
            }
            if (alpha_out) alpha_out[g_eid[p]] = aa;
        }
        int lim = min(32, e - base);
        #pragma unroll 4
        for (int t = 0; t < lim; t++) {
            int   c = __shfl_sync(0xffffffffu, cc, t);
            float a = __shfl_sync(0xffffffffu, aa, t);
            uint4 v = ((const uint4*)&g_Hb[c * 128])[lane];
            float2 f0 = __bfloat1622float2(*(__nv_bfloat162*)&v.x);
            float2 f1 = __bfloat1622float2(*(__nv_bfloat162*)&v.y);
            float2 f2 = __bfloat1622float2(*(__nv_bfloat162*)&v.z);
            float2 f3 = __bfloat1622float2(*(__nv_bfloat162*)&v.w);
            acc[0] += a * f0.x; acc[1] += a * f0.y;
            acc[2] += a * f1.x; acc[3] += a * f1.y;
            acc[4] += a * f2.x; acc[5] += a * f2.y;
            acc[6] += a * f3.x; acc[7] += a * f3.y;
        }
    }
    float4 o0, o1;
    const float4* bv = (const float4*)&bias[lane * 8];
    float4 b0 = bv[0], b1 = bv[1];
    o0.x = geluf(acc[0] + b0.x); o0.y = geluf(acc[1] + b0.y);
    o0.z = geluf(acc[2] + b0.z); o0.w = geluf(acc[3] + b0.w);
    o1.x = geluf(acc[4] + b1.x); o1.y = geluf(acc[5] + b1.y);
    o1.z = geluf(acc[6] + b1.z); o1.w = geluf(acc[7] + b1.w);
    float4* xp = (float4*)&g_X[d * 256 + lane * 8];
    xp[0] = o0; xp[1] = o1;
}

// ---------------- pooling (atomic-free, per-graph blocks) + MLP --------------
__global__ void __launch_bounds__(256) k_pool2() {
    __shared__ float sbuf[4][256];
    int g = blockIdx.x;
    int s = threadIdx.x >> 6, c4 = threadIdx.x & 63;
    int b = g_goff[g], e = g_goff[g + 1];
    float4 acc = make_float4(0, 0, 0, 0);
    for (int i = b + s; i < e; i += 4) {
        float4 v = *(const float4*)&g_X[i * 256 + c4 * 4];
        acc.x += v.x; acc.y += v.y; acc.z += v.z; acc.w += v.w;
    }
    *(float4*)&sbuf[s][c4 * 4] = acc;
    __syncthreads();
    if (s == 0) {
        #pragma unroll
        for (int k = 0; k < 4; k++) {
            int c = c4 * 4 + k;
            g_gsum[g * 256 + c] = sbuf[0][c] + sbuf[1][c] + sbuf[2][c] + sbuf[3][c];
        }
    }
}
__global__ void __launch_bounds__(512) k_mlp(const float* __restrict__ Wl1, const float* __restrict__ bl1,
                                             const float* __restrict__ Wl2, const float* __restrict__ bl2,
                                             const float* __restrict__ Wl3, const float* __restrict__ bl3,
                                             float* __restrict__ out) {
    __shared__ float G[16 * 256];
    __shared__ float G1[16 * 128];
    __shared__ float G2[16 * 64];
    int t = threadIdx.x;
    for (int i = t; i < 4096; i += 512) {
        int g = i >> 8;
        int cnt = g_goff[g + 1] - g_goff[g];
        G[i] = g_gsum[i] / (float)(cnt > 0 ? cnt : 1);
    }
    __syncthreads();
    for (int i = t; i < 2048; i += 512) {
        int gi = i >> 7, j = i & 127;
        float a = bl1[j];
        for (int k = 0; k < 256; k++) a += G[gi * 256 + k] * Wl1[k * 128 + j];
        G1[i] = geluf(a);
    }
    __syncthreads();
    for (int i = t; i < 1024; i += 512) {
        int gi = i >> 6, j = i & 63;
        float a = bl2[j];
        for (int k = 0; k < 128; k++) a += G1[gi * 128 + k] * Wl2[k * 64 + j];
        G2[i] = geluf(a);
    }
    __syncthreads();
    if (t < 16) {
        float a = bl3[0];
        for (int k = 0; k < 64; k++) a += G2[t * 64 + k] * Wl3[k];
        out[t] = 1.f / (1.f + expf(-a));
    }
}

// ---------------- attn_edge_index output --------------------------------------
__global__ void k_attn_idx(const void* __restrict__ ei, int E, int Etot,
                           float* __restrict__ dst) {
    int i = blockIdx.x * blockDim.x + threadIdx.x;
    if (i >= 2 * Etot) return;
    int which = i / Etot;
    int e = i - which * Etot;
    long long v = (e < E) ? load_idx(ei, (long long)which * E + e)
                          : (long long)(e - E);
    dst[i] = (float)v;
}

// ---------------- host launcher ------------------------------------------------
extern "C" void kernel_launch(void* const* d_in, const int* in_sizes, int n_in,
                              void* d_out, int out_size) {
    const float* x     = (const float*)d_in[0];
    const void*  ei    = d_in[1];
    const void*  batch = d_in[2];
    const float* W1  = (const float*)d_in[3];
    const float* as1 = (const float*)d_in[4];
    const float* ad1 = (const float*)d_in[5];
    const float* b1  = (const float*)d_in[6];
    const float* W2  = (const float*)d_in[7];
    const float* as2 = (const float*)d_in[8];
    const float* ad2 = (const float*)d_in[9];
    const float* b2  = (const float*)d_in[10];
    const float* Wl1 = (const float*)d_in[11];
    const float* bl1 = (const float*)d_in[12];
    const float* Wl2 = (const float*)d_in[13];
    const float* bl2 = (const float*)d_in[14];
    const float* Wl3 = (const float*)d_in[15];
    const float* bl3 = (const float*)d_in[16];

    int Nn = in_sizes[0];
    int E = in_sizes[1] / 2;
    int Etot = E + Nn;
    float* out = (float*)d_out;
    bool full = (out_size >= 16 + 3 * Etot);
    float* alpha_out = full ? (out + 16 + 2 * Etot) : nullptr;

    // ---- dtype detection (int32 vs int64 edge/batch arrays) ----
    k_detect<<<1, 256>>>((const int*)ei, 2 * E);

    // ---- CSR (counting sort by dst) + graph boundaries ----
    k_zero_deg<<<(Nn + 255) / 256, 256>>>(Nn);
    k_count<<<(Etot + 255) / 256, 256>>>(ei, E, Etot, Nn);
    k_scan<<<1, 1024>>>(Nn);
    k_fill<<<(Etot + 255) / 256, 256>>>(ei, E, Etot, Nn);
    k_bounds<<<(Nn + 255) / 256, 256>>>(batch, Nn);

    // ---- layer 1 (GATConv(1, 64, heads=4), rank-1 collapse, fused) ----
    k_prep1<<<1, 256>>>(W1, as1, ad1);
    k_sd1<<<(Nn + 255) / 256, 256>>>(x, Nn);
    k_fused1<<<(Nn + 7) / 8, 256>>>(x, W1, b1, Nn);

    // ---- layers 2-4 (GATConv(256, 256, heads=1)), fused softmax+agg ----
    for (int l = 0; l < 3; l++) {
        k_gemm<<<dim3((Nn + 127) / 128, 4), 256>>>(W2 + l * 65536,
                                                   as2 + l * 256, ad2 + l * 256, Nn);
        k_fatt<<<(Nn + 7) / 8, 256>>>(b2 + l * 256, Nn, (l == 2) ? alpha_out : nullptr);
    }

    // ---- mean pool + MLP head ----
    k_pool2<<<NGRAPH, 256>>>();
    k_mlp<<<1, 512>>>(Wl1, bl1, Wl2, bl2, Wl3, bl3, out);

    // ---- attn_edge_index output ----
    if (full) k_attn_idx<<<(2 * Etot + 255) / 256, 256>>>(ei, E, Etot, out + 16);
}

// round 7
// speedup vs baseline: 1.6013x; 1.0765x over previous
#include <cuda_runtime.h>
#include <cuda_bf16.h>
#include <math.h>

#define NMAX   20000
#define ETOT_MAX 340000
#define DD     256
#define NGRAPH 16

// ---------------- scratch (static device globals; no allocation) -------------
__device__ float    g_X[NMAX * DD];      // current features (layer input/output)
__device__ unsigned g_Hb[NMAX * 128];    // post-GEMM features, bf16x2 packed
__device__ float    g_as[NMAX * 4];      // L1: 4-head src logits; L2-4: 4 src partials
__device__ float    g_ad[NMAX * 4];      // L1: 4-head dst logits; L2-4: 4 dst partials
__device__ int      g_deg[NMAX];
__device__ int      g_row[NMAX + 1];
__device__ int      g_cur[NMAX];
__device__ int      g_col[ETOT_MAX];     // src node per CSR slot
__device__ int      g_eid[ETOT_MAX];     // original edge id per CSR slot
__device__ float    g_cs[4], g_cd[4];    // layer-1 collapsed attention weights
__device__ float    g_gsum[NGRAPH * DD];
__device__ int      g_goff[NGRAPH + 1];  // graph node-range boundaries (sorted batch)
__device__ int      g_is64;              // 1 if edge_index/batch are int64
__device__ int      g_done;              // pool->mlp intra-kernel flag

// ---------------- helpers ----------------------------------------------------
__device__ __forceinline__ float geluf(float x) {
    float t = tanhf(0.7978845608028654f * (x + 0.044715f * x * x * x));
    return 0.5f * x * (1.0f + t);
}
__device__ __forceinline__ float lrelu(float x) { return x > 0.f ? x : 0.2f * x; }

__device__ __forceinline__ long long load_idx(const void* p, long long i) {
    if (g_is64) return ((const long long*)p)[i];
    return (long long)((const int*)p)[i];
}

__device__ __forceinline__ unsigned f2tf32(float f) {
    unsigned r;
    asm("cvt.rna.tf32.f32 %0, %1;" : "=r"(r) : "f"(f));
    return r;
}
__device__ __forceinline__ void mma_tf32(float* c, const unsigned* a, const unsigned* b) {
    asm volatile(
        "mma.sync.aligned.m16n8k8.row.col.f32.tf32.tf32.f32 "
        "{%0,%1,%2,%3},{%4,%5,%6,%7},{%8,%9},{%0,%1,%2,%3};"
        : "+f"(c[0]), "+f"(c[1]), "+f"(c[2]), "+f"(c[3])
        : "r"(a[0]), "r"(a[1]), "r"(a[2]), "r"(a[3]), "r"(b[0]), "r"(b[1]));
}
__device__ __forceinline__ unsigned packbf2(float lo, float hi) {
    __nv_bfloat162 t = __floats2bfloat162_rn(lo, hi);
    return *(unsigned*)&t;
}

// ---- kernel 1: zero deg/done + dtype detect (block 1) + prep1 (block 0) -----
__global__ void __launch_bounds__(256) k_init(const int* __restrict__ ei32, int E,
                                              const float* __restrict__ W1,
                                              const float* __restrict__ as1,
                                              const float* __restrict__ ad1, int n) {
    int tid = threadIdx.x;
    int i = blockIdx.x * 256 + tid;
    if (i < n) g_deg[i] = 0;
    if (i == 0) g_done = 0;

    if (blockIdx.x == 1) {
        // dtype detection: int64 small values => odd 32-bit words all zero
        __shared__ int nz;
        if (tid == 0) nz = 0;
        __syncthreads();
        int pairs = E;                  // sample up to 4096 pairs of words
        int lim = min(pairs, 4096);
        for (int j = tid; j < lim; j += 256)
            if (ei32[2 * j + 1] != 0) nz = 1;
        __syncthreads();
        if (tid == 0) g_is64 = (nz == 0) ? 1 : 0;
    }
    if (blockIdx.x == 0) {
        // prep1: collapse W1 against per-head attention vectors
        __shared__ float ss[256], sd[256];
        float w = W1[tid];
        ss[tid] = w * as1[tid];
        sd[tid] = w * ad1[tid];
        __syncthreads();
        for (int off = 32; off; off >>= 1) {
            if ((tid & 63) < off) { ss[tid] += ss[tid + off]; sd[tid] += sd[tid + off]; }
            __syncthreads();
        }
        if ((tid & 63) == 0) { g_cs[tid >> 6] = ss[tid]; g_cd[tid >> 6] = sd[tid]; }
    }
}

// ---- kernel 2: degree count + layer-1 logits (sd1) + graph bounds -----------
__global__ void k_pre(const void* __restrict__ ei, const float* __restrict__ x,
                      const void* __restrict__ batch, int E, int Etot, int n) {
    int e = blockIdx.x * blockDim.x + threadIdx.x;
    if (e < Etot) {
        int dst = (e < E) ? (int)load_idx(ei, (long long)E + e) : (e - E);
        if (dst >= 0 && dst < n) atomicAdd(&g_deg[dst], 1);
    }
    if (e < n) {
        float xv = x[e];
        #pragma unroll
        for (int h = 0; h < 4; h++) {
            g_as[e * 4 + h] = xv * g_cs[h];
            g_ad[e * 4 + h] = xv * g_cd[h];
        }
        int b = (int)load_idx(batch, e);
        int prev = (e == 0) ? -1 : (int)load_idx(batch, e - 1);
        for (int g = prev + 1; g <= b && g <= NGRAPH; g++)
            if (g >= 0) g_goff[g] = e;
        if (e == n - 1)
            for (int g = b + 1; g <= NGRAPH; g++) g_goff[g] = n;
    }
}

// ---- kernel 3: coalesced two-phase scan --------------------------------------
__global__ void __launch_bounds__(1024) k_scan(int n) {
    __shared__ int sbuf[10240];
    __shared__ int wsum[32];
    int t = threadIdx.x, lane = t & 31, w = t >> 5;
    int carry = 0;
    #pragma unroll
    for (int ph = 0; ph < 2; ph++) {
        int base = ph * 10240;
        #pragma unroll
        for (int j = 0; j < 10; j++) {
            int idx = base + j * 1024 + t;
            sbuf[j * 1024 + t] = (idx < n) ? g_deg[idx] : 0;
        }
        __syncthreads();
        int vals[10], sum = 0;
        #pragma unroll
        for (int i = 0; i < 10; i++) { vals[i] = sbuf[t * 10 + i]; sum += vals[i]; }
        int s = sum;
        #pragma unroll
        for (int off = 1; off < 32; off <<= 1) {
            int v = __shfl_up_sync(0xffffffffu, s, off);
            if (lane >= off) s += v;
        }
        if (lane == 31) wsum[w] = s;
        __syncthreads();
        if (w == 0) {
            int x = wsum[lane];
            #pragma unroll
            for (int off = 1; off < 32; off <<= 1) {
                int v = __shfl_up_sync(0xffffffffu, x, off);
                if (lane >= off) x += v;
            }
            wsum[lane] = x;
        }
        __syncthreads();
        int excl = s - sum + (w > 0 ? wsum[w - 1] : 0) + carry;
        int total = wsum[31];
        __syncthreads();
        int run = excl;
        #pragma unroll
        for (int i = 0; i < 10; i++) { sbuf[t * 10 + i] = run; run += vals[i]; }
        __syncthreads();
        #pragma unroll
        for (int j = 0; j < 10; j++) {
            int idx = base + j * 1024 + t;
            if (idx < n) { int v = sbuf[j * 1024 + t]; g_row[idx] = v; g_cur[idx] = v; }
        }
        carry += total;
        __syncthreads();
    }
    if (t == 0) g_row[n] = carry;
}

// ---- kernel 4: CSR fill + attn_edge_index output (fused) --------------------
__global__ void k_fill(const void* __restrict__ ei, int E, int Etot, int n,
                       float* __restrict__ attn_dst) {
    int e = blockIdx.x * blockDim.x + threadIdx.x;
    if (e >= Etot) return;
    int src, dst;
    if (e < E) {
        src = (int)load_idx(ei, e);
        dst = (int)load_idx(ei, (long long)E + e);
    } else { src = e - E; dst = e - E; }
    if (attn_dst) {
        attn_dst[e] = (float)src;
        attn_dst[Etot + e] = (float)dst;
    }
    if (dst < 0 || dst >= n || src < 0 || src >= n) return;
    int pos = atomicAdd(&g_cur[dst], 1);
    g_col[pos] = src;
    g_eid[pos] = e;
}

// ---- fused layer-1: softmax (4 heads) + aggregate + W1 expand + gelu --------
__global__ void __launch_bounds__(256) k_fused1(const float* __restrict__ x,
                                                const float* __restrict__ W1,
                                                const float* __restrict__ b1, int n) {
    int wid = threadIdx.x >> 5, lane = threadIdx.x & 31;
    int d = blockIdx.x * 8 + wid;
    if (d >= n) return;
    int b = g_row[d], e = g_row[d + 1];
    float4 ad = ((const float4*)g_ad)[d];
    const int NC = 4;
    float4 ev[NC]; float xv[NC];
    float4 mx = make_float4(-1e30f, -1e30f, -1e30f, -1e30f);
    int i = 0;
    for (int p = b + lane; p < e; p += 32, i++) {
        int c = g_col[p];
        float4 av = ((const float4*)g_as)[c];
        float4 v;
        v.x = lrelu(av.x + ad.x); v.y = lrelu(av.y + ad.y);
        v.z = lrelu(av.z + ad.z); v.w = lrelu(av.w + ad.w);
        float xx = x[c];
        if (i < NC) { ev[i] = v; xv[i] = xx; }
        mx.x = fmaxf(mx.x, v.x); mx.y = fmaxf(mx.y, v.y);
        mx.z = fmaxf(mx.z, v.z); mx.w = fmaxf(mx.w, v.w);
    }
    #pragma unroll
    for (int o = 16; o; o >>= 1) {
        mx.x = fmaxf(mx.x, __shfl_xor_sync(0xffffffffu, mx.x, o));
        mx.y = fmaxf(mx.y, __shfl_xor_sync(0xffffffffu, mx.y, o));
        mx.z = fmaxf(mx.z, __shfl_xor_sync(0xffffffffu, mx.z, o));
        mx.w = fmaxf(mx.w, __shfl_xor_sync(0xffffffffu, mx.w, o));
    }
    float4 sm = make_float4(0, 0, 0, 0);
    i = 0;
    for (int p = b + lane; p < e; p += 32, i++) {
        float4 v;
        if (i < NC) v = ev[i];
        else {
            int c = g_col[p];
            float4 av = ((const float4*)g_as)[c];
            v.x = lrelu(av.x + ad.x); v.y = lrelu(av.y + ad.y);
            v.z = lrelu(av.z + ad.z); v.w = lrelu(av.w + ad.w);
        }
        v.x = expf(v.x - mx.x); v.y = expf(v.y - mx.y);
        v.z = expf(v.z - mx.z); v.w = expf(v.w - mx.w);
        if (i < NC) ev[i] = v;
        sm.x += v.x; sm.y += v.y; sm.z += v.z; sm.w += v.w;
    }
    #pragma unroll
    for (int o = 16; o; o >>= 1) {
        sm.x += __shfl_xor_sync(0xffffffffu, sm.x, o);
        sm.y += __shfl_xor_sync(0xffffffffu, sm.y, o);
        sm.z += __shfl_xor_sync(0xffffffffu, sm.z, o);
        sm.w += __shfl_xor_sync(0xffffffffu, sm.w, o);
    }
    float4 inv;
    inv.x = 1.f / (sm.x + 1e-16f); inv.y = 1.f / (sm.y + 1e-16f);
    inv.z = 1.f / (sm.z + 1e-16f); inv.w = 1.f / (sm.w + 1e-16f);
    float4 acc = make_float4(0, 0, 0, 0);
    i = 0;
    for (int p = b + lane; p < e; p += 32, i++) {
        float4 al; float xx;
        if (i < NC) { al = ev[i]; xx = xv[i]; }
        else {
            int c = g_col[p];
            float4 av = ((const float4*)g_as)[c];
            al.x = expf(lrelu(av.x + ad.x) - mx.x);
            al.y = expf(lrelu(av.y + ad.y) - mx.y);
            al.z = expf(lrelu(av.z + ad.z) - mx.z);
            al.w = expf(lrelu(av.w + ad.w) - mx.w);
            xx = x[c];
        }
        acc.x += al.x * inv.x * xx; acc.y += al.y * inv.y * xx;
        acc.z += al.z * inv.z * xx; acc.w += al.w * inv.w * xx;
    }
    #pragma unroll
    for (int o = 16; o; o >>= 1) {
        acc.x += __shfl_xor_sync(0xffffffffu, acc.x, o);
        acc.y += __shfl_xor_sync(0xffffffffu, acc.y, o);
        acc.z += __shfl_xor_sync(0xffffffffu, acc.z, o);
        acc.w += __shfl_xor_sync(0xffffffffu, acc.w, o);
    }
    int head = lane >> 3;
    float hv = (head == 0) ? acc.x : (head == 1) ? acc.y : (head == 2) ? acc.z : acc.w;
    int c0 = lane * 8;
    const float4* wp = (const float4*)&W1[c0];
    const float4* bp = (const float4*)&b1[c0];
    float4 w0 = wp[0], w1 = wp[1], bb0 = bp[0], bb1 = bp[1];
    float4 o0, o1;
    o0.x = geluf(hv * w0.x + bb0.x); o0.y = geluf(hv * w0.y + bb0.y);
    o0.z = geluf(hv * w0.z + bb0.z); o0.w = geluf(hv * w0.w + bb0.w);
    o1.x = geluf(hv * w1.x + bb1.x); o1.y = geluf(hv * w1.y + bb1.y);
    o1.z = geluf(hv * w1.z + bb1.z); o1.w = geluf(hv * w1.w + bb1.w);
    float4* xp = (float4*)&g_X[d * 256 + c0];
    xp[0] = o0; xp[1] = o1;
}

// ---------------- tf32 TC GEMM + deterministic partial logit epilogue --------
__global__ void __launch_bounds__(256) k_gemm(const float* __restrict__ B,
                                              const float* __restrict__ att_s,
                                              const float* __restrict__ att_d, int M) {
    __shared__ unsigned As[32][136];
    __shared__ unsigned Bs[32][72];
    __shared__ float s_pas[128], s_pad[128];
    int tid = threadIdx.x;
    int lane = tid & 31;
    int wid = tid >> 5;
    int wm = (wid & 3) * 32;
    int wng = wid >> 2;
    int wn = wng * 32;
    int m0 = blockIdx.x * 128;
    int n0 = blockIdx.y * 64;

    float acc[2][4][4];
    #pragma unroll
    for (int mi = 0; mi < 2; mi++)
        #pragma unroll
        for (int ni = 0; ni < 4; ni++)
            #pragma unroll
            for (int q = 0; q < 4; q++) acc[mi][ni][q] = 0.f;

    int am = tid & 31;
    int ak = 4 * (tid >> 5);
    int bn = 4 * (tid & 15);
    int bk = tid >> 4;

    float4 va[4], vb[2];
    #pragma unroll
    for (int p = 0; p < 4; p++) {
        int gm = m0 + p * 32 + am;
        va[p] = make_float4(0, 0, 0, 0);
        if (gm < M) va[p] = *(const float4*)&g_X[gm * 256 + ak];
    }
    #pragma unroll
    for (int p = 0; p < 2; p++)
        vb[p] = *(const float4*)&B[(bk + p * 16) * 256 + n0 + bn];

    for (int k0 = 0; k0 < 256; k0 += 32) {
        #pragma unroll
        for (int p = 0; p < 4; p++) {
            int sm_ = p * 32 + am;
            As[ak + 0][sm_] = f2tf32(va[p].x);
            As[ak + 1][sm_] = f2tf32(va[p].y);
            As[ak + 2][sm_] = f2tf32(va[p].z);
            As[ak + 3][sm_] = f2tf32(va[p].w);
        }
        #pragma unroll
        for (int p = 0; p < 2; p++) {
            int kk = bk + p * 16;
            Bs[kk][bn + 0] = f2tf32(vb[p].x);
            Bs[kk][bn + 1] = f2tf32(vb[p].y);
            Bs[kk][bn + 2] = f2tf32(vb[p].z);
            Bs[kk][bn + 3] = f2tf32(vb[p].w);
        }
        __syncthreads();
        if (k0 + 32 < 256) {
            int kn = k0 + 32;
            #pragma unroll
            for (int p = 0; p < 4; p++) {
                int gm = m0 + p * 32 + am;
                va[p] = make_float4(0, 0, 0, 0);
                if (gm < M) va[p] = *(const float4*)&g_X[gm * 256 + kn + ak];
            }
            #pragma unroll
            for (int p = 0; p < 2; p++)
                vb[p] = *(const float4*)&B[(kn + bk + p * 16) * 256 + n0 + bn];
        }
        #pragma unroll
        for (int ks = 0; ks < 4; ks++) {
            int kb = ks * 8;
            int c4 = lane & 3, r8 = lane >> 2;
            unsigned a[2][4], bf[4][2];
            #pragma unroll
            for (int mi = 0; mi < 2; mi++) {
                int mr = wm + mi * 16 + r8;
                a[mi][0] = As[kb + c4][mr];
                a[mi][1] = As[kb + c4][mr + 8];
                a[mi][2] = As[kb + c4 + 4][mr];
                a[mi][3] = As[kb + c4 + 4][mr + 8];
            }
            #pragma unroll
            for (int ni = 0; ni < 4; ni++) {
                int nc = wn + ni * 8 + r8;
                bf[ni][0] = Bs[kb + c4][nc];
                bf[ni][1] = Bs[kb + c4 + 4][nc];
            }
            #pragma unroll
            for (int mi = 0; mi < 2; mi++)
                #pragma unroll
                for (int ni = 0; ni < 4; ni++)
                    mma_tf32(acc[mi][ni], a[mi], bf[ni]);
        }
        __syncthreads();
    }
    int r8 = lane >> 2, c4 = lane & 3;
    float pas[4] = {0, 0, 0, 0}, pad_[4] = {0, 0, 0, 0};
    #pragma unroll
    for (int mi = 0; mi < 2; mi++) {
        int m = m0 + wm + mi * 16 + r8;
        #pragma unroll
        for (int ni = 0; ni < 4; ni++) {
            int nn = n0 + wn + ni * 8 + 2 * c4;
            float s0 = __ldg(&att_s[nn]), s1 = __ldg(&att_s[nn + 1]);
            float d0 = __ldg(&att_d[nn]), d1 = __ldg(&att_d[nn + 1]);
            pas[2 * mi]     += acc[mi][ni][0] * s0 + acc[mi][ni][1] * s1;
            pas[2 * mi + 1] += acc[mi][ni][2] * s0 + acc[mi][ni][3] * s1;
            pad_[2 * mi]     += acc[mi][ni][0] * d0 + acc[mi][ni][1] * d1;
            pad_[2 * mi + 1] += acc[mi][ni][2] * d0 + acc[mi][ni][3] * d1;
            if (m < M)
                g_Hb[m * 128 + (nn >> 1)] = packbf2(acc[mi][ni][0], acc[mi][ni][1]);
            if (m + 8 < M)
                g_Hb[(m + 8) * 128 + (nn >> 1)] = packbf2(acc[mi][ni][2], acc[mi][ni][3]);
        }
    }
    #pragma unroll
    for (int off = 1; off < 4; off <<= 1) {
        #pragma unroll
        for (int r = 0; r < 4; r++) {
            pas[r]  += __shfl_xor_sync(0xffffffffu, pas[r], off);
            pad_[r] += __shfl_xor_sync(0xffffffffu, pad_[r], off);
        }
    }
    if (c4 == 0 && wng == 1) {
        #pragma unroll
        for (int r = 0; r < 4; r++) {
            int row = wm + r8 + (r & 1) * 8 + (r >> 1) * 16;
            s_pas[row] = pas[r]; s_pad[row] = pad_[r];
        }
    }
    __syncthreads();
    if (c4 == 0 && wng == 0) {
        #pragma unroll
        for (int r = 0; r < 4; r++) {
            int row = wm + r8 + (r & 1) * 8 + (r >> 1) * 16;
            int m = m0 + row;
            if (m < M) {
                g_as[m * 4 + blockIdx.y] = pas[r] + s_pas[row];
                g_ad[m * 4 + blockIdx.y] = pad_[r] + s_pad[row];
            }
        }
    }
}

// ------- fused edge softmax + aggregation (layers 2-4), warp per dst ---------
__global__ void __launch_bounds__(256) k_fatt(const float* __restrict__ bias, int n,
                                              float* __restrict__ alpha_out) {
    int wid = threadIdx.x >> 5, lane = threadIdx.x & 31;
    int d = blockIdx.x * 8 + wid;
    if (d >= n) return;
    int b = g_row[d], e = g_row[d + 1];
    float4 dv = ((const float4*)g_ad)[d];
    float ad = (dv.x + dv.y) + (dv.z + dv.w);
    const int NC = 8;
    float ev[NC]; int col[NC];
    float mx = -1e30f;
    int i = 0;
    for (int p = b + lane; p < e; p += 32, i++) {
        int c = g_col[p];
        float4 sv = ((const float4*)g_as)[c];
        float v = lrelu((sv.x + sv.y) + (sv.z + sv.w) + ad);
        if (i < NC) { ev[i] = v; col[i] = c; }
        mx = fmaxf(mx, v);
    }
    #pragma unroll
    for (int o = 16; o; o >>= 1) mx = fmaxf(mx, __shfl_xor_sync(0xffffffffu, mx, o));
    float sm = 0.f;
    i = 0;
    for (int p = b + lane; p < e; p += 32, i++) {
        float v;
        if (i < NC) v = ev[i];
        else {
            float4 sv = ((const float4*)g_as)[g_col[p]];
            v = lrelu((sv.x + sv.y) + (sv.z + sv.w) + ad);
        }
        v = expf(v - mx);
        if (i < NC) ev[i] = v;
        sm += v;
    }
    #pragma unroll
    for (int o = 16; o; o >>= 1) sm += __shfl_xor_sync(0xffffffffu, sm, o);
    float inv = 1.f / (sm + 1e-16f);

    float acc[8];
    #pragma unroll
    for (int j = 0; j < 8; j++) acc[j] = 0.f;
    for (int base = b; base < e; base += 32) {
        int p = base + lane;
        int idx = (base - b) >> 5;
        float aa = 0.f; int cc = 0;
        if (p < e) {
            if (idx < NC) { aa = ev[idx] * inv; cc = col[idx]; }
            else {
                cc = g_col[p];
                float4 sv = ((const float4*)g_as)[cc];
                aa = expf(lrelu((sv.x + sv.y) + (sv.z + sv.w) + ad) - mx) * inv;
            }
            if (alpha_out) alpha_out[g_eid[p]] = aa;
        }
        int lim = min(32, e - base);
        #pragma unroll 4
        for (int t = 0; t < lim; t++) {
            int   c = __shfl_sync(0xffffffffu, cc, t);
            float a = __shfl_sync(0xffffffffu, aa, t);
            uint4 v = ((const uint4*)&g_Hb[c * 128])[lane];
            float2 f0 = __bfloat1622float2(*(__nv_bfloat162*)&v.x);
            float2 f1 = __bfloat1622float2(*(__nv_bfloat162*)&v.y);
            float2 f2 = __bfloat1622float2(*(__nv_bfloat162*)&v.z);
            float2 f3 = __bfloat1622float2(*(__nv_bfloat162*)&v.w);
            acc[0] += a * f0.x; acc[1] += a * f0.y;
            acc[2] += a * f1.x; acc[3] += a * f1.y;
            acc[4] += a * f2.x; acc[5] += a * f2.y;
            acc[6] += a * f3.x; acc[7] += a * f3.y;
        }
    }
    float4 o0, o1;
    const float4* bv = (const float4*)&bias[lane * 8];
    float4 b0 = bv[0], b1 = bv[1];
    o0.x = geluf(acc[0] + b0.x); o0.y = geluf(acc[1] + b0.y);
    o0.z = geluf(acc[2] + b0.z); o0.w = geluf(acc[3] + b0.w);
    o1.x = geluf(acc[4] + b1.x); o1.y = geluf(acc[5] + b1.y);
    o1.z = geluf(acc[6] + b1.z); o1.w = geluf(acc[7] + b1.w);
    float4* xp = (float4*)&g_X[d * 256 + lane * 8];
    xp[0] = o0; xp[1] = o1;
}

// ---- kernel: pool (blocks 0-15) + MLP head (block 16, spin-wait) ------------
__global__ void __launch_bounds__(512) k_poolmlp(const float* __restrict__ Wl1, const float* __restrict__ bl1,
                                                 const float* __restrict__ Wl2, const float* __restrict__ bl2,
                                                 const float* __restrict__ Wl3, const float* __restrict__ bl3,
                                                 float* __restrict__ out) {
    int t = threadIdx.x;
    if (blockIdx.x < NGRAPH) {
        __shared__ float sbuf[8][256];
        int g = blockIdx.x;
        int s = t >> 6, c4 = t & 63;          // 8 row-groups x 64 float4 channels
        int b = g_goff[g], e = g_goff[g + 1];
        float4 acc = make_float4(0, 0, 0, 0);
        for (int i = b + s; i < e; i += 8) {
            float4 v = *(const float4*)&g_X[i * 256 + c4 * 4];
            acc.x += v.x; acc.y += v.y; acc.z += v.z; acc.w += v.w;
        }
        *(float4*)&sbuf[s][c4 * 4] = acc;
        __syncthreads();
        if (s == 0) {
            #pragma unroll
            for (int k = 0; k < 4; k++) {
                int c = c4 * 4 + k;
                float v = 0.f;
                #pragma unroll
                for (int r = 0; r < 8; r++) v += sbuf[r][c];
                g_gsum[g * 256 + c] = v;
            }
        }
        __threadfence();
        __syncthreads();
        if (t == 0) atomicAdd(&g_done, 1);
        return;
    }
    // MLP block: wait for all 16 pool blocks
    if (t == 0) {
        while (atomicAdd(&g_done, 0) < NGRAPH) __nanosleep(200);
    }
    __syncthreads();
    __threadfence();
    __shared__ float G[16 * 256];
    __shared__ float G1[16 * 128];
    __shared__ float G2[16 * 64];
    for (int i = t; i < 4096; i += 512) {
        int g = i >> 8;
        int cnt = g_goff[g + 1] - g_goff[g];
        G[i] = g_gsum[i] / (float)(cnt > 0 ? cnt : 1);
    }
    __syncthreads();
    for (int i = t; i < 2048; i += 512) {
        int gi = i >> 7, j = i & 127;
        float a = bl1[j];
        for (int k = 0; k < 256; k++) a += G[gi * 256 + k] * Wl1[k * 128 + j];
        G1[i] = geluf(a);
    }
    __syncthreads();
    for (int i = t; i < 1024; i += 512) {
        int gi = i >> 6, j = i & 63;
        float a = bl2[j];
        for (int k = 0; k < 128; k++) a += G1[gi * 128 + k] * Wl2[k * 64 + j];
        G2[i] = geluf(a);
    }
    __syncthreads();
    if (t < 16) {
        float a = bl3[0];
        for (int k = 0; k < 64; k++) a += G2[t * 64 + k] * Wl3[k];
        out[t] = 1.f / (1.f + expf(-a));
    }
}

// ---------------- host launcher ------------------------------------------------
extern "C" void kernel_launch(void* const* d_in, const int* in_sizes, int n_in,
                              void* d_out, int out_size) {
    const float* x     = (const float*)d_in[0];
    const void*  ei    = d_in[1];
    const void*  batch = d_in[2];
    const float* W1  = (const float*)d_in[3];
    const float* as1 = (const float*)d_in[4];
    const float* ad1 = (const float*)d_in[5];
    const float* b1  = (const float*)d_in[6];
    const float* W2  = (const float*)d_in[7];
    const float* as2 = (const float*)d_in[8];
    const float* ad2 = (const float*)d_in[9];
    const float* b2  = (const float*)d_in[10];
    const float* Wl1 = (const float*)d_in[11];
    const float* bl1 = (const float*)d_in[12];
    const float* Wl2 = (const float*)d_in[13];
    const float* bl2 = (const float*)d_in[14];
    const float* Wl3 = (const float*)d_in[15];
    const float* bl3 = (const float*)d_in[16];

    int Nn = in_sizes[0];
    int E = in_sizes[1] / 2;
    int Etot = E + Nn;
    float* out = (float*)d_out;
    bool full = (out_size >= 16 + 3 * Etot);
    float* attn_out  = full ? (out + 16) : nullptr;
    float* alpha_out = full ? (out + 16 + 2 * Etot) : nullptr;

    // 1: zero + dtype detect + prep1
    k_init<<<(Nn + 255) / 256, 256>>>((const int*)ei, E, W1, as1, ad1, Nn);
    // 2: degree count + layer-1 logits + graph bounds
    k_pre<<<(Etot + 255) / 256, 256>>>(ei, x, batch, E, Etot, Nn);
    // 3: prefix scan
    k_scan<<<1, 1024>>>(Nn);
    // 4: CSR fill + attn_edge_index
    k_fill<<<(Etot + 255) / 256, 256>>>(ei, E, Etot, Nn, attn_out);
    // 5: fused layer 1
    k_fused1<<<(Nn + 7) / 8, 256>>>(x, W1, b1, Nn);
    // 6-11: layers 2-4
    for (int l = 0; l < 3; l++) {
        k_gemm<<<dim3((Nn + 127) / 128, 4), 256>>>(W2 + l * 65536,
                                                   as2 + l * 256, ad2 + l * 256, Nn);
        k_fatt<<<(Nn + 7) / 8, 256>>>(b2 + l * 256, Nn, (l == 2) ? alpha_out : nullptr);
    }
    // 12: pool + MLP head in one kernel
    k_poolmlp<<<NGRAPH + 1, 512>>>(Wl1, bl1, Wl2, bl2, Wl3, bl3, out);
}

// round 9
// speedup vs baseline: 2.0050x; 1.2521x over previous
#include <cuda_runtime.h>
#include <cuda_bf16.h>
#include <math.h>
#include <stdint.h>

#define NMAX   20000
#define ETOT_MAX 340000
#define DD     256
#define NGRAPH 16

// ---------------- scratch (static device globals; no allocation) -------------
__device__ float    g_X[NMAX * DD];      // current features (layer input/output)
__device__ unsigned g_Hb[NMAX * 128];    // post-GEMM features, bf16x2 packed
__device__ float    g_as[NMAX * 4];      // L1: 4-head src logits; L2-4: 4 src partials
__device__ float    g_ad[NMAX * 4];      // L1: 4-head dst logits; L2-4: 4 dst partials
__device__ int      g_deg[NMAX];         // zero-initialized; re-zeroed by k_scan
__device__ int      g_row[NMAX + 1];
__device__ int      g_cur[NMAX];
__device__ int      g_col[ETOT_MAX];
__device__ int      g_eid[ETOT_MAX];
__device__ float    g_gsum[NGRAPH * DD];
__device__ int      g_goff[NGRAPH + 1];
__device__ int      g_is64;
__device__ int      g_done;              // pool->mlp counter
__device__ int      g_done2;             // fill-phase completion counter
__device__ int      g_tkt;               // fill-phase ticket counter

// ---------------- helpers ----------------------------------------------------
__device__ __forceinline__ float geluf(float x) {
    float t = tanhf(0.7978845608028654f * (x + 0.044715f * x * x * x));
    return 0.5f * x * (1.0f + t);
}
__device__ __forceinline__ float lrelu(float x) { return x > 0.f ? x : 0.2f * x; }

__device__ __forceinline__ long long load_idx(const void* p, long long i) {
    if (g_is64) return ((const long long*)p)[i];
    return (long long)((const int*)p)[i];
}
__device__ __forceinline__ long long load_idx2(const void* p, long long i, int is64) {
    if (is64) return ((const long long*)p)[i];
    return (long long)((const int*)p)[i];
}
__device__ __forceinline__ void mma_tf32(float* c, const unsigned* a, const unsigned* b) {
    asm volatile(
        "mma.sync.aligned.m16n8k8.row.col.f32.tf32.tf32.f32 "
        "{%0,%1,%2,%3},{%4,%5,%6,%7},{%8,%9},{%0,%1,%2,%3};"
        : "+f"(c[0]), "+f"(c[1]), "+f"(c[2]), "+f"(c[3])
        : "r"(a[0]), "r"(a[1]), "r"(a[2]), "r"(a[3]), "r"(b[0]), "r"(b[1]));
}
__device__ __forceinline__ unsigned packbf2(float lo, float hi) {
    __nv_bfloat162 t = __floats2bfloat162_rn(lo, hi);
    return *(unsigned*)&t;
}

// ---- kernel 1: per-block detect + prep1 + deg count + sd1 + bounds ----------
__global__ void __launch_bounds__(256) k_pre(const void* __restrict__ ei,
                                             const float* __restrict__ x,
                                             const void* __restrict__ batch,
                                             const float* __restrict__ W1,
                                             const float* __restrict__ as1,
                                             const float* __restrict__ ad1,
                                             int E, int Etot, int n) {
    __shared__ int nz;
    __shared__ float ss[256], sd[256];
    __shared__ float scs[4], scd[4];
    int tid = threadIdx.x;
    if (tid == 0) nz = 0;
    __syncthreads();
    // dtype detect (int64 small values => odd 32-bit words all zero)
    const int* w32 = (const int*)ei;
    int lim = min(E, 4096);
    for (int j = tid; j < lim; j += 256)
        if (w32[2 * j + 1] != 0) nz = 1;
    // prep1 collapse: sum W1[c]*att[c] per head
    float w = W1[tid];
    ss[tid] = w * as1[tid];
    sd[tid] = w * ad1[tid];
    __syncthreads();
    int is64 = (nz == 0) ? 1 : 0;
    for (int off = 32; off; off >>= 1) {
        if ((tid & 63) < off) { ss[tid] += ss[tid + off]; sd[tid] += sd[tid + off]; }
        __syncthreads();
    }
    if ((tid & 63) == 0) { scs[tid >> 6] = ss[tid]; scd[tid >> 6] = sd[tid]; }
    __syncthreads();

    int e = blockIdx.x * 256 + tid;
    if (e == 0) { g_done = 0; g_done2 = 0; g_tkt = 0; g_is64 = is64; }
    if (e < Etot) {
        int dst = (e < E) ? (int)load_idx2(ei, (long long)E + e, is64) : (e - E);
        if (dst >= 0 && dst < n) atomicAdd(&g_deg[dst], 1);
    }
    if (e < n) {
        float xv = x[e];
        #pragma unroll
        for (int h = 0; h < 4; h++) {
            g_as[e * 4 + h] = xv * scs[h];
            g_ad[e * 4 + h] = xv * scd[h];
        }
        int b = (int)load_idx2(batch, e, is64);
        int prev = (e == 0) ? -1 : (int)load_idx2(batch, e - 1, is64);
        for (int g = prev + 1; g <= b && g <= NGRAPH; g++)
            if (g >= 0) g_goff[g] = e;
        if (e == n - 1)
            for (int g = b + 1; g <= NGRAPH; g++) g_goff[g] = n;
    }
}

// ---- kernel 2: coalesced two-phase scan (self-cleans g_deg) ------------------
__global__ void __launch_bounds__(1024) k_scan(int n) {
    __shared__ int sbuf[10240];
    __shared__ int wsum[32];
    int t = threadIdx.x, lane = t & 31, w = t >> 5;
    int carry = 0;
    #pragma unroll
    for (int ph = 0; ph < 2; ph++) {
        int base = ph * 10240;
        #pragma unroll
        for (int j = 0; j < 10; j++) {
            int idx = base + j * 1024 + t;
            int v = (idx < n) ? g_deg[idx] : 0;
            sbuf[j * 1024 + t] = v;
            if (idx < n) g_deg[idx] = 0;   // re-zero for next replay
        }
        __syncthreads();
        int vals[10], sum = 0;
        #pragma unroll
        for (int i = 0; i < 10; i++) { vals[i] = sbuf[t * 10 + i]; sum += vals[i]; }
        int s = sum;
        #pragma unroll
        for (int off = 1; off < 32; off <<= 1) {
            int v = __shfl_up_sync(0xffffffffu, s, off);
            if (lane >= off) s += v;
        }
        if (lane == 31) wsum[w] = s;
        __syncthreads();
        if (w == 0) {
            int x = wsum[lane];
            #pragma unroll
            for (int off = 1; off < 32; off <<= 1) {
                int v = __shfl_up_sync(0xffffffffu, x, off);
                if (lane >= off) x += v;
            }
            wsum[lane] = x;
        }
        __syncthreads();
        int excl = s - sum + (w > 0 ? wsum[w - 1] : 0) + carry;
        int total = wsum[31];
        __syncthreads();
        int run = excl;
        #pragma unroll
        for (int i = 0; i < 10; i++) { sbuf[t * 10 + i] = run; run += vals[i]; }
        __syncthreads();
        #pragma unroll
        for (int j = 0; j < 10; j++) {
            int idx = base + j * 1024 + t;
            if (idx < n) { int v = sbuf[j * 1024 + t]; g_row[idx] = v; g_cur[idx] = v; }
        }
        carry += total;
        __syncthreads();
    }
    if (t == 0) g_row[n] = carry;
}

// ---- kernel 3: CSR fill (ticket queue) + attn idx + fused layer 1 -----------
__global__ void __launch_bounds__(256) k_fillf1(const void* __restrict__ ei,
                                                int E, int Etot, int n, int NBfill,
                                                float* __restrict__ attn_dst,
                                                const float* __restrict__ x,
                                                const float* __restrict__ W1,
                                                const float* __restrict__ b1) {
    int tid = threadIdx.x;
    __shared__ int schunk;
    int mychunks = 0;
    // ---- phase 1: fill chunks via work-claiming (forward-progress safe) ----
    for (;;) {
        if (tid == 0) schunk = atomicAdd(&g_tkt, 1);
        __syncthreads();
        int chunk = schunk;
        __syncthreads();
        if (chunk >= NBfill) break;
        mychunks++;
        int e = chunk * 256 + tid;
        if (e < Etot) {
            int src, dst;
            if (e < E) {
                src = (int)load_idx(ei, e);
                dst = (int)load_idx(ei, (long long)E + e);
            } else { src = e - E; dst = e - E; }
            if (attn_dst) {
                attn_dst[e] = (float)src;
                attn_dst[Etot + e] = (float)dst;
            }
            if (dst >= 0 && dst < n && src >= 0 && src < n) {
                int pos = atomicAdd(&g_cur[dst], 1);
                g_col[pos] = src;
                g_eid[pos] = e;
            }
        }
    }
    __threadfence();
    __syncthreads();
    if (tid == 0) {
        if (mychunks) atomicAdd(&g_done2, mychunks);
        while (atomicAdd(&g_done2, 0) < NBfill) __nanosleep(100);
    }
    __syncthreads();
    __threadfence();
    // ---- phase 2: fused layer 1 (softmax 4 heads + agg + W1 expand) ----
    int wid = tid >> 5, lane = tid & 31;
    int d = blockIdx.x * 8 + wid;
    if (d >= n) return;
    int b = g_row[d], e2 = g_row[d + 1];
    float4 ad = ((const float4*)g_ad)[d];
    const int NC = 4;
    float4 ev[NC]; float xv[NC];
    float4 mx = make_float4(-1e30f, -1e30f, -1e30f, -1e30f);
    int i = 0;
    for (int p = b + lane; p < e2; p += 32, i++) {
        int c = g_col[p];
        float4 av = ((const float4*)g_as)[c];
        float4 v;
        v.x = lrelu(av.x + ad.x); v.y = lrelu(av.y + ad.y);
        v.z = lrelu(av.z + ad.z); v.w = lrelu(av.w + ad.w);
        float xx = x[c];
        if (i < NC) { ev[i] = v; xv[i] = xx; }
        mx.x = fmaxf(mx.x, v.x); mx.y = fmaxf(mx.y, v.y);
        mx.z = fmaxf(mx.z, v.z); mx.w = fmaxf(mx.w, v.w);
    }
    #pragma unroll
    for (int o = 16; o; o >>= 1) {
        mx.x = fmaxf(mx.x, __shfl_xor_sync(0xffffffffu, mx.x, o));
        mx.y = fmaxf(mx.y, __shfl_xor_sync(0xffffffffu, mx.y, o));
        mx.z = fmaxf(mx.z, __shfl_xor_sync(0xffffffffu, mx.z, o));
        mx.w = fmaxf(mx.w, __shfl_xor_sync(0xffffffffu, mx.w, o));
    }
    float4 sm = make_float4(0, 0, 0, 0);
    i = 0;
    for (int p = b + lane; p < e2; p += 32, i++) {
        float4 v;
        if (i < NC) v = ev[i];
        else {
            int c = g_col[p];
            float4 av = ((const float4*)g_as)[c];
            v.x = lrelu(av.x + ad.x); v.y = lrelu(av.y + ad.y);
            v.z = lrelu(av.z + ad.z); v.w = lrelu(av.w + ad.w);
        }
        v.x = expf(v.x - mx.x); v.y = expf(v.y - mx.y);
        v.z = expf(v.z - mx.z); v.w = expf(v.w - mx.w);
        if (i < NC) ev[i] = v;
        sm.x += v.x; sm.y += v.y; sm.z += v.z; sm.w += v.w;
    }
    #pragma unroll
    for (int o = 16; o; o >>= 1) {
        sm.x += __shfl_xor_sync(0xffffffffu, sm.x, o);
        sm.y += __shfl_xor_sync(0xffffffffu, sm.y, o);
        sm.z += __shfl_xor_sync(0xffffffffu, sm.z, o);
        sm.w += __shfl_xor_sync(0xffffffffu, sm.w, o);
    }
    float4 inv;
    inv.x = 1.f / (sm.x + 1e-16f); inv.y = 1.f / (sm.y + 1e-16f);
    inv.z = 1.f / (sm.z + 1e-16f); inv.w = 1.f / (sm.w + 1e-16f);
    float4 acc = make_float4(0, 0, 0, 0);
    i = 0;
    for (int p = b + lane; p < e2; p += 32, i++) {
        float4 al; float xx;
        if (i < NC) { al = ev[i]; xx = xv[i]; }
        else {
            int c = g_col[p];
            float4 av = ((const float4*)g_as)[c];
            al.x = expf(lrelu(av.x + ad.x) - mx.x);
            al.y = expf(lrelu(av.y + ad.y) - mx.y);
            al.z = expf(lrelu(av.z + ad.z) - mx.z);
            al.w = expf(lrelu(av.w + ad.w) - mx.w);
            xx = x[c];
        }
        acc.x += al.x * inv.x * xx; acc.y += al.y * inv.y * xx;
        acc.z += al.z * inv.z * xx; acc.w += al.w * inv.w * xx;
    }
    #pragma unroll
    for (int o = 16; o; o >>= 1) {
        acc.x += __shfl_xor_sync(0xffffffffu, acc.x, o);
        acc.y += __shfl_xor_sync(0xffffffffu, acc.y, o);
        acc.z += __shfl_xor_sync(0xffffffffu, acc.z, o);
        acc.w += __shfl_xor_sync(0xffffffffu, acc.w, o);
    }
    int head = lane >> 3;
    float hv = (head == 0) ? acc.x : (head == 1) ? acc.y : (head == 2) ? acc.z : acc.w;
    int c0 = lane * 8;
    const float4* wp = (const float4*)&W1[c0];
    const float4* bp = (const float4*)&b1[c0];
    float4 w0 = wp[0], w1 = wp[1], bb0 = bp[0], bb1 = bp[1];
    float4 o0, o1;
    o0.x = geluf(hv * w0.x + bb0.x); o0.y = geluf(hv * w0.y + bb0.y);
    o0.z = geluf(hv * w0.z + bb0.z); o0.w = geluf(hv * w0.w + bb0.w);
    o1.x = geluf(hv * w1.x + bb1.x); o1.y = geluf(hv * w1.y + bb1.y);
    o1.z = geluf(hv * w1.z + bb1.z); o1.w = geluf(hv * w1.w + bb1.w);
    float4* xp = (float4*)&g_X[d * 256 + c0];
    xp[0] = o0; xp[1] = o1;
}

// ---- tf32 TC GEMM: 3-stage cp.async pipeline, raw-f32-as-tf32 ---------------
// dyn smem: A [3][128][36] + B [3][32][72] floats = 82944 bytes
#define AST 4608
#define BOFF 13824
#define BST 2304
__global__ void __launch_bounds__(256) k_gemm(const float* __restrict__ B,
                                              const float* __restrict__ att_s,
                                              const float* __restrict__ att_d, int M) {
    extern __shared__ float smf[];
    __shared__ float s_pas[128], s_pad[128];
    uint32_t sbase;
    asm("{ .reg .u64 t; cvta.to.shared.u64 t, %1; cvt.u32.u64 %0, t; }"
        : "=r"(sbase) : "l"(smf));
    int tid = threadIdx.x;
    int lane = tid & 31;
    int wid = tid >> 5;
    int wm = (wid & 3) * 32;
    int wng = wid >> 2;
    int wn = wng * 32;
    int m0 = blockIdx.x * 128;
    int n0 = blockIdx.y * 64;

    float acc[2][4][4];
    #pragma unroll
    for (int mi = 0; mi < 2; mi++)
        #pragma unroll
        for (int ni = 0; ni < 4; ni++)
            #pragma unroll
            for (int q = 0; q < 4; q++) acc[mi][ni][q] = 0.f;

    auto load_stage = [&](int s, int k0) {
        #pragma unroll
        for (int i = 0; i < 4; i++) {
            int g = tid + i * 256;
            int m = g >> 3, kq = (g & 7) * 4;
            int gm = m0 + m;
            const float* src = &g_X[(long long)((gm < M) ? gm : 0) * 256 + k0 + kq];
            uint32_t dst = sbase + (s * AST + m * 36 + kq) * 4;
            int sz = (gm < M) ? 16 : 0;
            asm volatile("cp.async.cg.shared.global [%0],[%1],16,%2;"
                         :: "r"(dst), "l"(src), "r"(sz));
        }
        #pragma unroll
        for (int i = 0; i < 2; i++) {
            int g = tid + i * 256;
            int k = g >> 4, nq = (g & 15) * 4;
            const float* src = &B[(k0 + k) * 256 + n0 + nq];
            uint32_t dst = sbase + (BOFF + s * BST + k * 72 + nq) * 4;
            asm volatile("cp.async.cg.shared.global [%0],[%1],16,%2;"
                         :: "r"(dst), "l"(src), "r"(16));
        }
        asm volatile("cp.async.commit_group;");
    };

    load_stage(0, 0);
    load_stage(1, 32);
    const unsigned* smu = (const unsigned*)smf;
    int c4 = lane & 3, r8 = lane >> 2;

    for (int it = 0; it < 8; it++) {
        int s = it % 3;
        if (it < 7) asm volatile("cp.async.wait_group 1;");
        else        asm volatile("cp.async.wait_group 0;");
        __syncthreads();
        if (it < 6) load_stage((it + 2) % 3, (it + 2) * 32);
        #pragma unroll
        for (int ks = 0; ks < 4; ks++) {
            int kb = ks * 8;
            unsigned a[2][4], bf[4][2];
            #pragma unroll
            for (int mi = 0; mi < 2; mi++) {
                int mr = wm + mi * 16 + r8;
                a[mi][0] = smu[s * AST + mr * 36 + kb + c4];
                a[mi][1] = smu[s * AST + (mr + 8) * 36 + kb + c4];
                a[mi][2] = smu[s * AST + mr * 36 + kb + c4 + 4];
                a[mi][3] = smu[s * AST + (mr + 8) * 36 + kb + c4 + 4];
            }
            #pragma unroll
            for (int ni = 0; ni < 4; ni++) {
                int nc = wn + ni * 8 + r8;
                bf[ni][0] = smu[BOFF + s * BST + (kb + c4) * 72 + nc];
                bf[ni][1] = smu[BOFF + s * BST + (kb + c4 + 4) * 72 + nc];
            }
            #pragma unroll
            for (int mi = 0; mi < 2; mi++)
                #pragma unroll
                for (int ni = 0; ni < 4; ni++)
                    mma_tf32(acc[mi][ni], a[mi], bf[ni]);
        }
    }
    // epilogue: bf16 H store + deterministic partial logits
    float pas[4] = {0, 0, 0, 0}, pad_[4] = {0, 0, 0, 0};
    #pragma unroll
    for (int mi = 0; mi < 2; mi++) {
        int m = m0 + wm + mi * 16 + r8;
        #pragma unroll
        for (int ni = 0; ni < 4; ni++) {
            int nn = n0 + wn + ni * 8 + 2 * c4;
            float s0 = __ldg(&att_s[nn]), s1 = __ldg(&att_s[nn + 1]);
            float d0 = __ldg(&att_d[nn]), d1 = __ldg(&att_d[nn + 1]);
            pas[2 * mi]     += acc[mi][ni][0] * s0 + acc[mi][ni][1] * s1;
            pas[2 * mi + 1] += acc[mi][ni][2] * s0 + acc[mi][ni][3] * s1;
            pad_[2 * mi]     += acc[mi][ni][0] * d0 + acc[mi][ni][1] * d1;
            pad_[2 * mi + 1] += acc[mi][ni][2] * d0 + acc[mi][ni][3] * d1;
            if (m < M)
                g_Hb[m * 128 + (nn >> 1)] = packbf2(acc[mi][ni][0], acc[mi][ni][1]);
            if (m + 8 < M)
                g_Hb[(m + 8) * 128 + (nn >> 1)] = packbf2(acc[mi][ni][2], acc[mi][ni][3]);
        }
    }
    #pragma unroll
    for (int off = 1; off < 4; off <<= 1) {
        #pragma unroll
        for (int r = 0; r < 4; r++) {
            pas[r]  += __shfl_xor_sync(0xffffffffu, pas[r], off);
            pad_[r] += __shfl_xor_sync(0xffffffffu, pad_[r], off);
        }
    }
    if (c4 == 0 && wng == 1) {
        #pragma unroll
        for (int r = 0; r < 4; r++) {
            int row = wm + r8 + (r & 1) * 8 + (r >> 1) * 16;
            s_pas[row] = pas[r]; s_pad[row] = pad_[r];
        }
    }
    __syncthreads();
    if (c4 == 0 && wng == 0) {
        #pragma unroll
        for (int r = 0; r < 4; r++) {
            int row = wm + r8 + (r & 1) * 8 + (r >> 1) * 16;
            int m = m0 + row;
            if (m < M) {
                g_as[m * 4 + blockIdx.y] = pas[r] + s_pas[row];
                g_ad[m * 4 + blockIdx.y] = pad_[r] + s_pad[row];
            }
        }
    }
}

// ------- fused edge softmax + aggregation (layers 2-4), warp per dst ---------
__global__ void __launch_bounds__(256) k_fatt(const float* __restrict__ bias, int n,
                                              float* __restrict__ alpha_out) {
    int wid = threadIdx.x >> 5, lane = threadIdx.x & 31;
    int d = blockIdx.x * 8 + wid;
    if (d >= n) return;
    int b = g_row[d], e = g_row[d + 1];
    float4 dv = ((const float4*)g_ad)[d];
    float ad = (dv.x + dv.y) + (dv.z + dv.w);
    const int NC = 8;
    float ev[NC]; int col[NC];
    float mx = -1e30f;
    int i = 0;
    for (int p = b + lane; p < e; p += 32, i++) {
        int c = g_col[p];
        float4 sv = ((const float4*)g_as)[c];
        float v = lrelu((sv.x + sv.y) + (sv.z + sv.w) + ad);
        if (i < NC) { ev[i] = v; col[i] = c; }
        mx = fmaxf(mx, v);
    }
    #pragma unroll
    for (int o = 16; o; o >>= 1) mx = fmaxf(mx, __shfl_xor_sync(0xffffffffu, mx, o));
    float sm = 0.f;
    i = 0;
    for (int p = b + lane; p < e; p += 32, i++) {
        float v;
        if (i < NC) v = ev[i];
        else {
            float4 sv = ((const float4*)g_as)[g_col[p]];
            v = lrelu((sv.x + sv.y) + (sv.z + sv.w) + ad);
        }
        v = expf(v - mx);
        if (i < NC) ev[i] = v;
        sm += v;
    }
    #pragma unroll
    for (int o = 16; o; o >>= 1) sm += __shfl_xor_sync(0xffffffffu, sm, o);
    float inv = 1.f / (sm + 1e-16f);

    float acc[8];
    #pragma unroll
    for (int j = 0; j < 8; j++) acc[j] = 0.f;
    for (int base = b; base < e; base += 32) {
        int p = base + lane;
        int idx = (base - b) >> 5;
        float aa = 0.f; int cc = 0;
        if (p < e) {
            if (idx < NC) { aa = ev[idx] * inv; cc = col[idx]; }
            else {
                cc = g_col[p];
                float4 sv = ((const float4*)g_as)[cc];
                aa = expf(lrelu((sv.x + sv.y) + (sv.z + sv.w) + ad) - mx) * inv;
            }
            if (alpha_out) alpha_out[g_eid[p]] = aa;
        }
        int lim = min(32, e - base);
        #pragma unroll 8
        for (int t = 0; t < lim; t++) {
            int   c = __shfl_sync(0xffffffffu, cc, t);
            float a = __shfl_sync(0xffffffffu, aa, t);
            uint4 v = ((const uint4*)&g_Hb[c * 128])[lane];
            float2 f0 = __bfloat1622float2(*(__nv_bfloat162*)&v.x);
            float2 f1 = __bfloat1622float2(*(__nv_bfloat162*)&v.y);
            float2 f2 = __bfloat1622float2(*(__nv_bfloat162*)&v.z);
            float2 f3 = __bfloat1622float2(*(__nv_bfloat162*)&v.w);
            acc[0] += a * f0.x; acc[1] += a * f0.y;
            acc[2] += a * f1.x; acc[3] += a * f1.y;
            acc[4] += a * f2.x; acc[5] += a * f2.y;
            acc[6] += a * f3.x; acc[7] += a * f3.y;
        }
    }
    float4 o0, o1;
    const float4* bv = (const float4*)&bias[lane * 8];
    float4 b0 = bv[0], b1 = bv[1];
    o0.x = geluf(acc[0] + b0.x); o0.y = geluf(acc[1] + b0.y);
    o0.z = geluf(acc[2] + b0.z); o0.w = geluf(acc[3] + b0.w);
    o1.x = geluf(acc[4] + b1.x); o1.y = geluf(acc[5] + b1.y);
    o1.z = geluf(acc[6] + b1.z); o1.w = geluf(acc[7] + b1.w);
    float4* xp = (float4*)&g_X[d * 256 + lane * 8];
    xp[0] = o0; xp[1] = o1;
}

// ---- pool (blocks 0-15) + MLP head (block 16, spin-wait) --------------------
__global__ void __launch_bounds__(512) k_poolmlp(const float* __restrict__ Wl1, const float* __restrict__ bl1,
                                                 const float* __restrict__ Wl2, const float* __restrict__ bl2,
                                                 const float* __restrict__ Wl3, const float* __restrict__ bl3,
                                                 float* __restrict__ out) {
    int t = threadIdx.x;
    if (blockIdx.x < NGRAPH) {
        __shared__ float sbuf[8][256];
        int g = blockIdx.x;
        int s = t >> 6, c4 = t & 63;
        int b = g_goff[g], e = g_goff[g + 1];
        float4 acc = make_float4(0, 0, 0, 0);
        for (int i = b + s; i < e; i += 8) {
            float4 v = *(const float4*)&g_X[i * 256 + c4 * 4];
            acc.x += v.x; acc.y += v.y; acc.z += v.z; acc.w += v.w;
        }
        *(float4*)&sbuf[s][c4 * 4] = acc;
        __syncthreads();
        if (s == 0) {
            #pragma unroll
            for (int k = 0; k < 4; k++) {
                int c = c4 * 4 + k;
                float v = 0.f;
                #pragma unroll
                for (int r = 0; r < 8; r++) v += sbuf[r][c];
                g_gsum[g * 256 + c] = v;
            }
        }
        __threadfence();
        __syncthreads();
        if (t == 0) atomicAdd(&g_done, 1);
        return;
    }
    if (t == 0) {
        while (atomicAdd(&g_done, 0) < NGRAPH) __nanosleep(200);
    }
    __syncthreads();
    __threadfence();
    __shared__ float G[16 * 256];
    __shared__ float G1[16 * 128];
    __shared__ float G2[16 * 64];
    for (int i = t; i < 4096; i += 512) {
        int g = i >> 8;
        int cnt = g_goff[g + 1] - g_goff[g];
        G[i] = g_gsum[i] / (float)(cnt > 0 ? cnt : 1);
    }
    __syncthreads();
    for (int i = t; i < 2048; i += 512) {
        int gi = i >> 7, j = i & 127;
        float a = bl1[j];
        for (int k = 0; k < 256; k++) a += G[gi * 256 + k] * Wl1[k * 128 + j];
        G1[i] = geluf(a);
    }
    __syncthreads();
    for (int i = t; i < 1024; i += 512) {
        int gi = i >> 6, j = i & 63;
        float a = bl2[j];
        for (int k = 0; k < 128; k++) a += G1[gi * 128 + k] * Wl2[k * 64 + j];
        G2[i] = geluf(a);
    }
    __syncthreads();
    if (t < 16) {
        float a = bl3[0];
        for (int k = 0; k < 64; k++) a += G2[t * 64 + k] * Wl3[k];
        out[t] = 1.f / (1.f + expf(-a));
    }
}

// ---------------- host launcher ------------------------------------------------
extern "C" void kernel_launch(void* const* d_in, const int* in_sizes, int n_in,
                              void* d_out, int out_size) {
    const float* x     = (const float*)d_in[0];
    const void*  ei    = d_in[1];
    const void*  batch = d_in[2];
    const float* W1  = (const float*)d_in[3];
    const float* as1 = (const float*)d_in[4];
    const float* ad1 = (const float*)d_in[5];
    const float* b1  = (const float*)d_in[6];
    const float* W2  = (const float*)d_in[7];
    const float* as2 = (const float*)d_in[8];
    const float* ad2 = (const float*)d_in[9];
    const float* b2  = (const float*)d_in[10];
    const float* Wl1 = (const float*)d_in[11];
    const float* bl1 = (const float*)d_in[12];
    const float* Wl2 = (const float*)d_in[13];
    const float* bl2 = (const float*)d_in[14];
    const float* Wl3 = (const float*)d_in[15];
    const float* bl3 = (const float*)d_in[16];

    int Nn = in_sizes[0];
    int E = in_sizes[1] / 2;
    int Etot = E + Nn;
    float* out = (float*)d_out;
    bool full = (out_size >= 16 + 3 * Etot);
    float* attn_out  = full ? (out + 16) : nullptr;
    float* alpha_out = full ? (out + 16 + 2 * Etot) : nullptr;

    int NBfill = (Etot + 255) / 256;
    int NBf1   = (Nn + 7) / 8;
    int NBgrid = (NBf1 > NBfill) ? NBf1 : NBfill;

    cudaFuncSetAttribute(k_gemm, cudaFuncAttributeMaxDynamicSharedMemorySize, 82944);

    // 1: detect + prep1 + deg count + sd1 + bounds + counter reset
    k_pre<<<(Etot + 255) / 256, 256>>>(ei, x, batch, W1, as1, ad1, E, Etot, Nn);
    // 2: prefix scan (self-cleans g_deg)
    k_scan<<<1, 1024>>>(Nn);
    // 3: CSR fill + attn idx + fused layer 1
    k_fillf1<<<NBgrid, 256>>>(ei, E, Etot, Nn, NBfill, attn_out, x, W1, b1);
    // 4-9: layers 2-4
    for (int l = 0; l < 3; l++) {
        k_gemm<<<dim3((Nn + 127) / 128, 4), 256, 82944>>>(W2 + l * 65536,
                                                          as2 + l * 256, ad2 + l * 256, Nn);
        k_fatt<<<(Nn + 7) / 8, 256>>>(b2 + l * 256, Nn, (l == 2) ? alpha_out : nullptr);
    }
    // 10: pool + MLP head
    k_poolmlp<<<NGRAPH + 1, 512>>>(Wl1, bl1, Wl2, bl2, Wl3, bl3, out);
}